// round 1
// baseline (speedup 1.0000x reference)
#include <cuda_runtime.h>

#define MAX_N 50000
#define F1 128
#define F2 64

// -------- scratch (static __device__ arrays; no allocation allowed) --------
__device__ float g_h1[MAX_N * F1];    // x@W1, later overwritten with relu(agg1+self+b1)
__device__ float g_agg1[MAX_N * F1];  // layer-1 neighbor aggregation
__device__ float g_h2[MAX_N * F2];    // h1relu @ W2
__device__ float g_deg[MAX_N];
__device__ float g_dinv[MAX_N];
__device__ int   g_is64;              // 1 if edge_index is int64, 0 if int32

// -------- dtype detection for edge_index (int64 vs int32) --------
__global__ void detect_kernel(const void* ei, int E) {
    __shared__ int bad;
    if (threadIdx.x == 0) bad = 0;
    __syncthreads();
    const long long* p = (const long long*)ei;
    int samples = E < 2048 ? E : 2048;
    for (int i = threadIdx.x; i < samples; i += blockDim.x) {
        long long v = p[i];
        if (v < 0 || v >= (long long)MAX_N) bad = 1;
    }
    __syncthreads();
    if (threadIdx.x == 0) g_is64 = bad ? 0 : 1;  // any out-of-range int64 => data is int32
}

__device__ __forceinline__ int edge_at(const void* ei, int idx) {
    if (g_is64) return (int)((const long long*)ei)[idx];
    return ((const int*)ei)[idx];
}

// -------- degree / norm --------
__global__ void init_deg_kernel(int n) {
    int i = blockIdx.x * blockDim.x + threadIdx.x;
    if (i < n) g_deg[i] = 1.0f;   // self-loop contributes 1 to every node's degree
}

__global__ void deg_count_kernel(const void* ei, int E) {
    int e = blockIdx.x * blockDim.x + threadIdx.x;
    if (e >= E) return;
    int d = edge_at(ei, E + e);   // dst row of edge_index [2, E]
    atomicAdd(&g_deg[d], 1.0f);   // no return use -> RED
}

__global__ void dinv_kernel(int n) {
    int i = blockIdx.x * blockDim.x + threadIdx.x;
    if (i < n) g_dinv[i] = rsqrtf(g_deg[i]);  // deg >= 1 always
}

// -------- tiled fp32 GEMM: C[M,BN] = A[M,128] @ W[128,BN] --------
template<int BN, int TM, int TN>
__global__ void gemm_kernel(const float* __restrict__ A, const float* __restrict__ W,
                            float* __restrict__ C, int M) {
    constexpr int BM = 64, BK = 16, K = F1;
    constexpr int TX = BN / TN;            // threads along N
    __shared__ float sA[BK][BM];
    __shared__ float sB[BK][BN];
    int tid = threadIdx.x;                 // 256 threads
    int tx = tid % TX;
    int ty = tid / TX;                     // 256/TX rows of TM each == BM
    int rowBase = blockIdx.x * BM;

    float acc[TM][TN];
#pragma unroll
    for (int i = 0; i < TM; i++)
#pragma unroll
        for (int j = 0; j < TN; j++) acc[i][j] = 0.0f;

    for (int k0 = 0; k0 < K; k0 += BK) {
        // load A tile (BM x BK), transposed into sA[k][row]
        for (int i4 = tid; i4 < BM * BK / 4; i4 += blockDim.x) {
            int r  = (i4 * 4) / BK;
            int kk = (i4 * 4) % BK;
            int gr = rowBase + r;
            float4 v = make_float4(0.f, 0.f, 0.f, 0.f);
            if (gr < M) v = *(const float4*)&A[(size_t)gr * K + k0 + kk];
            sA[kk + 0][r] = v.x; sA[kk + 1][r] = v.y;
            sA[kk + 2][r] = v.z; sA[kk + 3][r] = v.w;
        }
        // load W tile (BK x BN)
        for (int i4 = tid; i4 < BK * BN / 4; i4 += blockDim.x) {
            int kk = (i4 * 4) / BN;
            int c  = (i4 * 4) % BN;
            *(float4*)&sB[kk][c] = *(const float4*)&W[(size_t)(k0 + kk) * BN + c];
        }
        __syncthreads();
#pragma unroll
        for (int kk = 0; kk < BK; kk++) {
            float ra[TM], rb[TN];
#pragma unroll
            for (int i = 0; i < TM; i++) ra[i] = sA[kk][ty * TM + i];
#pragma unroll
            for (int j = 0; j < TN; j++) rb[j] = sB[kk][tx * TN + j];
#pragma unroll
            for (int i = 0; i < TM; i++)
#pragma unroll
                for (int j = 0; j < TN; j++) acc[i][j] += ra[i] * rb[j];
        }
        __syncthreads();
    }
#pragma unroll
    for (int i = 0; i < TM; i++) {
        int r = rowBase + ty * TM + i;
        if (r >= M) continue;
#pragma unroll
        for (int j = 0; j < TN; j += 4) {
            *(float4*)&C[(size_t)r * BN + tx * TN + j] =
                make_float4(acc[i][j], acc[i][j + 1], acc[i][j + 2], acc[i][j + 3]);
        }
    }
}

// -------- edge scatter, layer 1: one warp per edge, 128 floats, red.v4 --------
__global__ void scatter1_kernel(const void* ei, int E) {
    int w    = blockIdx.x * (blockDim.x >> 5) + (threadIdx.x >> 5);
    int lane = threadIdx.x & 31;
    if (w >= E) return;
    int s = edge_at(ei, w);
    int d = edge_at(ei, E + w);
    float nrm = g_dinv[s] * g_dinv[d];
    float4 v = ((const float4*)(g_h1 + (size_t)s * F1))[lane];
    float a = v.x * nrm, b = v.y * nrm, c = v.z * nrm, e = v.w * nrm;
    float* dp = g_agg1 + (size_t)d * F1 + lane * 4;
    asm volatile("red.global.add.v4.f32 [%0], {%1, %2, %3, %4};"
                 :: "l"(dp), "f"(a), "f"(b), "f"(c), "f"(e) : "memory");
}

// -------- edge scatter, layer 2: one warp per edge, 64 floats, red.v2 --------
__global__ void scatter2_kernel(const void* ei, int E, float* __restrict__ out) {
    int w    = blockIdx.x * (blockDim.x >> 5) + (threadIdx.x >> 5);
    int lane = threadIdx.x & 31;
    if (w >= E) return;
    int s = edge_at(ei, w);
    int d = edge_at(ei, E + w);
    float nrm = g_dinv[s] * g_dinv[d];
    float2 v = ((const float2*)(g_h2 + (size_t)s * F2))[lane];
    float a = v.x * nrm, b = v.y * nrm;
    float* dp = out + (size_t)d * F2 + lane * 2;
    asm volatile("red.global.add.v2.f32 [%0], {%1, %2};"
                 :: "l"(dp), "f"(a), "f"(b) : "memory");
}

// -------- epilogue 1: h1 = relu(agg1 + dinv^2 * h1 + b1)  (self-loop folded in) --------
__global__ void epi1_kernel(const float* __restrict__ b1, int n) {
    int idx = blockIdx.x * blockDim.x + threadIdx.x;   // over n * (F1/4) float4s
    if (idx >= n * (F1 / 4)) return;
    int i = idx >> 5;            // node (F1/4 == 32)
    int q = idx & 31;            // float4 column
    float di = g_dinv[i];
    float self = di * di;
    float4 a = ((const float4*)g_agg1)[idx];
    float4 h = ((const float4*)g_h1)[idx];
    float4 bb = ((const float4*)b1)[q];
    float4 r;
    r.x = fmaxf(fmaf(self, h.x, a.x) + bb.x, 0.0f);
    r.y = fmaxf(fmaf(self, h.y, a.y) + bb.y, 0.0f);
    r.z = fmaxf(fmaf(self, h.z, a.z) + bb.z, 0.0f);
    r.w = fmaxf(fmaf(self, h.w, a.w) + bb.w, 0.0f);
    ((float4*)g_h1)[idx] = r;
}

// -------- epilogue 2: out += dinv^2 * h2 + b2 --------
__global__ void epi2_kernel(const float* __restrict__ b2, float* __restrict__ out, int n) {
    int idx = blockIdx.x * blockDim.x + threadIdx.x;   // over n * (F2/4) float4s
    if (idx >= n * (F2 / 4)) return;
    int i = idx >> 4;            // node (F2/4 == 16)
    int q = idx & 15;
    float di = g_dinv[i];
    float self = di * di;
    float4 o = ((float4*)out)[idx];
    float4 h = ((const float4*)g_h2)[idx];
    float4 bb = ((const float4*)b2)[q];
    o.x = fmaf(self, h.x, o.x) + bb.x;
    o.y = fmaf(self, h.y, o.y) + bb.y;
    o.z = fmaf(self, h.z, o.z) + bb.z;
    o.w = fmaf(self, h.w, o.w) + bb.w;
    ((float4*)out)[idx] = o;
}

extern "C" void kernel_launch(void* const* d_in, const int* in_sizes, int n_in,
                              void* d_out, int out_size) {
    const float* x  = (const float*)d_in[0];
    const void*  ei = d_in[1];
    const float* W1 = (const float*)d_in[2];
    const float* b1 = (const float*)d_in[3];
    const float* W2 = (const float*)d_in[4];
    const float* b2 = (const float*)d_in[5];
    float* out = (float*)d_out;

    int n = in_sizes[0] / F1;      // 50000
    int E = in_sizes[1] / 2;       // 800000

    float *p_h1, *p_agg1, *p_h2;
    cudaGetSymbolAddress((void**)&p_h1,   g_h1);
    cudaGetSymbolAddress((void**)&p_agg1, g_agg1);
    cudaGetSymbolAddress((void**)&p_h2,   g_h2);

    cudaMemsetAsync(p_agg1, 0, (size_t)n * F1 * sizeof(float));
    cudaMemsetAsync(out,    0, (size_t)n * F2 * sizeof(float));

    detect_kernel<<<1, 256>>>(ei, E);
    init_deg_kernel<<<(n + 255) / 256, 256>>>(n);
    deg_count_kernel<<<(E + 255) / 256, 256>>>(ei, E);
    dinv_kernel<<<(n + 255) / 256, 256>>>(n);

    // layer 1: h1 = x @ W1
    gemm_kernel<F1, 4, 8><<<(n + 63) / 64, 256>>>(x, W1, p_h1, n);
    scatter1_kernel<<<(E * 32 + 255) / 256, 256>>>(ei, E);
    epi1_kernel<<<(n * (F1 / 4) + 255) / 256, 256>>>(b1, n);

    // layer 2: h2 = relu_h @ W2
    gemm_kernel<F2, 4, 4><<<(n + 63) / 64, 256>>>(p_h1, W2, p_h2, n);
    scatter2_kernel<<<(E * 32 + 255) / 256, 256>>>(ei, E, out);
    epi2_kernel<<<(n * (F2 / 4) + 255) / 256, 256>>>(b2, out, n);
}

// round 2
// speedup vs baseline: 1.5120x; 1.5120x over previous
#include <cuda_runtime.h>

#define MAX_N 50000
#define MAX_E 800000
#define F1 128
#define F2 64

// -------- scratch (static __device__ arrays; no allocation allowed) --------
__device__ float g_h1[MAX_N * F1];    // x@W1
__device__ float g_hr[MAX_N * F1];    // relu(agg1 + self + b1)
__device__ float g_h2[MAX_N * F2];    // hr @ W2
__device__ float g_dinv[MAX_N];
__device__ int   g_cnt[MAX_N];        // histogram of dst
__device__ int   g_rowptr[MAX_N + 1];
__device__ int   g_cursor[MAX_N];
__device__ int   g_srcs[MAX_E];       // CSR: src node per (dst-sorted) edge
__device__ int   g_is64;

// -------- dtype detection for edge_index (int64 vs int32) --------
__global__ void detect_kernel(const void* ei, int E) {
    __shared__ int bad;
    if (threadIdx.x == 0) bad = 0;
    __syncthreads();
    const long long* p = (const long long*)ei;
    int samples = E < 2048 ? E : 2048;
    for (int i = threadIdx.x; i < samples; i += blockDim.x) {
        long long v = p[i];
        if (v < 0 || v >= (long long)MAX_N) bad = 1;
    }
    __syncthreads();
    if (threadIdx.x == 0) g_is64 = bad ? 0 : 1;
}

__device__ __forceinline__ int edge_at(const void* ei, int idx) {
    if (g_is64) return (int)((const long long*)ei)[idx];
    return ((const int*)ei)[idx];
}

// -------- CSR construction --------
__global__ void hist_kernel(const void* ei, int E) {
    int e = blockIdx.x * blockDim.x + threadIdx.x;
    if (e >= E) return;
    atomicAdd(&g_cnt[edge_at(ei, E + e)], 1);
}

// single-block exclusive scan of g_cnt -> g_rowptr, g_cursor (shfl-based)
__global__ void scan_kernel(int n) {
    __shared__ int warpsum[32];
    __shared__ int carry;
    int t = threadIdx.x, lane = t & 31, w = t >> 5;
    if (t == 0) carry = 0;
    __syncthreads();
    for (int base = 0; base < n; base += 1024) {
        int i = base + t;
        int v = (i < n) ? g_cnt[i] : 0;
        int x = v;
#pragma unroll
        for (int o = 1; o < 32; o <<= 1) {
            int y = __shfl_up_sync(~0u, x, o);
            if (lane >= o) x += y;
        }
        if (lane == 31) warpsum[w] = x;
        __syncthreads();
        if (w == 0) {
            int s = warpsum[lane];
#pragma unroll
            for (int o = 1; o < 32; o <<= 1) {
                int y = __shfl_up_sync(~0u, s, o);
                if (lane >= o) s += y;
            }
            warpsum[lane] = s;
        }
        __syncthreads();
        int wbase = (w == 0) ? 0 : warpsum[w - 1];
        int excl = carry + wbase + x - v;
        if (i < n) { g_rowptr[i] = excl; g_cursor[i] = excl; }
        __syncthreads();
        if (t == 0) carry += warpsum[31];
        __syncthreads();
    }
    if (t == 0) g_rowptr[n] = carry;
}

__global__ void dinv_kernel(int n) {
    int i = blockIdx.x * blockDim.x + threadIdx.x;
    if (i < n) {
        int deg = g_rowptr[i + 1] - g_rowptr[i] + 1;  // +1 self-loop
        g_dinv[i] = rsqrtf((float)deg);
    }
}

__global__ void build_kernel(const void* ei, int E) {
    int e = blockIdx.x * blockDim.x + threadIdx.x;
    if (e >= E) return;
    int s = edge_at(ei, e);
    int d = edge_at(ei, E + e);
    int pos = atomicAdd(&g_cursor[d], 1);
    g_srcs[pos] = s;
}

// -------- tiled fp32 GEMM: C[M,BN] = A[M,128] @ W[128,BN], 8x8 register tile --------
template<int BN, int TN>
__global__ void gemm_kernel(const float* __restrict__ A, const float* __restrict__ W,
                            float* __restrict__ C, int M) {
    constexpr int BM = 128, BK = 16, K = F1, TM = 8;
    constexpr int TX = BN / TN;              // threads along N
    __shared__ float sA[BK][BM];
    __shared__ float sB[BK][BN];
    int tid = threadIdx.x;                   // 256 threads
    int tx = tid % TX;
    int ty = tid / TX;                       // (256/TX)*TM == BM
    int rowBase = blockIdx.x * BM;

    float acc[TM][TN];
#pragma unroll
    for (int i = 0; i < TM; i++)
#pragma unroll
        for (int j = 0; j < TN; j++) acc[i][j] = 0.0f;

    for (int k0 = 0; k0 < K; k0 += BK) {
        // A tile: BM x BK floats = BM*BK/4 float4s, transposed into sA[k][m]
#pragma unroll
        for (int i4 = tid; i4 < BM * BK / 4; i4 += 256) {
            int r  = i4 / (BK / 4);
            int kk = (i4 % (BK / 4)) * 4;
            int gr = rowBase + r;
            float4 v = make_float4(0.f, 0.f, 0.f, 0.f);
            if (gr < M) v = *(const float4*)&A[(size_t)gr * K + k0 + kk];
            sA[kk + 0][r] = v.x; sA[kk + 1][r] = v.y;
            sA[kk + 2][r] = v.z; sA[kk + 3][r] = v.w;
        }
        // W tile: BK x BN
#pragma unroll
        for (int i4 = tid; i4 < BK * BN / 4; i4 += 256) {
            int kk = (i4 * 4) / BN;
            int c  = (i4 * 4) % BN;
            *(float4*)&sB[kk][c] = *(const float4*)&W[(size_t)(k0 + kk) * BN + c];
        }
        __syncthreads();
#pragma unroll
        for (int kk = 0; kk < BK; kk++) {
            float ra[TM], rb[TN];
#pragma unroll
            for (int i = 0; i < TM; i++) ra[i] = sA[kk][ty * TM + i];
#pragma unroll
            for (int j = 0; j < TN; j++) rb[j] = sB[kk][tx * TN + j];
#pragma unroll
            for (int i = 0; i < TM; i++)
#pragma unroll
                for (int j = 0; j < TN; j++) acc[i][j] += ra[i] * rb[j];
        }
        __syncthreads();
    }
#pragma unroll
    for (int i = 0; i < TM; i++) {
        int r = rowBase + ty * TM + i;
        if (r >= M) continue;
#pragma unroll
        for (int j = 0; j < TN; j += 4) {
            *(float4*)&C[(size_t)r * BN + tx * TN + j] =
                make_float4(acc[i][j], acc[i][j + 1], acc[i][j + 2], acc[i][j + 3]);
        }
    }
}

// -------- aggregation layer 1: warp per node, fused self-loop + bias + relu --------
__global__ void agg1_kernel(const float* __restrict__ b1, int n) {
    int w    = (blockIdx.x * blockDim.x + threadIdx.x) >> 5;
    int lane = threadIdx.x & 31;
    if (w >= n) return;
    float di = g_dinv[w];
    const float4* h = (const float4*)g_h1;
    float4 v = h[(size_t)w * 32 + lane];
    float4 acc = make_float4(di * v.x, di * v.y, di * v.z, di * v.w);  // self-loop
    int j  = g_rowptr[w];
    int jE = g_rowptr[w + 1];
    for (; j + 1 < jE; j += 2) {
        int   sa = g_srcs[j],  sb = g_srcs[j + 1];
        float wa = g_dinv[sa], wb = g_dinv[sb];
        float4 ma = h[(size_t)sa * 32 + lane];
        float4 mb = h[(size_t)sb * 32 + lane];
        acc.x += wa * ma.x + wb * mb.x;
        acc.y += wa * ma.y + wb * mb.y;
        acc.z += wa * ma.z + wb * mb.z;
        acc.w += wa * ma.w + wb * mb.w;
    }
    if (j < jE) {
        int   sa = g_srcs[j];
        float wa = g_dinv[sa];
        float4 ma = h[(size_t)sa * 32 + lane];
        acc.x += wa * ma.x; acc.y += wa * ma.y;
        acc.z += wa * ma.z; acc.w += wa * ma.w;
    }
    float4 bb = ((const float4*)b1)[lane];
    float4 r;
    r.x = fmaxf(fmaf(acc.x, di, bb.x), 0.0f);
    r.y = fmaxf(fmaf(acc.y, di, bb.y), 0.0f);
    r.z = fmaxf(fmaf(acc.z, di, bb.z), 0.0f);
    r.w = fmaxf(fmaf(acc.w, di, bb.w), 0.0f);
    ((float4*)g_hr)[(size_t)w * 32 + lane] = r;
}

// -------- aggregation layer 2: warp per node, fused self-loop + bias --------
__global__ void agg2_kernel(const float* __restrict__ b2, float* __restrict__ out, int n) {
    int w    = (blockIdx.x * blockDim.x + threadIdx.x) >> 5;
    int lane = threadIdx.x & 31;
    if (w >= n) return;
    float di = g_dinv[w];
    const float2* h = (const float2*)g_h2;
    float2 v = h[(size_t)w * 32 + lane];
    float2 acc = make_float2(di * v.x, di * v.y);
    int j  = g_rowptr[w];
    int jE = g_rowptr[w + 1];
    for (; j + 1 < jE; j += 2) {
        int   sa = g_srcs[j],  sb = g_srcs[j + 1];
        float wa = g_dinv[sa], wb = g_dinv[sb];
        float2 ma = h[(size_t)sa * 32 + lane];
        float2 mb = h[(size_t)sb * 32 + lane];
        acc.x += wa * ma.x + wb * mb.x;
        acc.y += wa * ma.y + wb * mb.y;
    }
    if (j < jE) {
        int   sa = g_srcs[j];
        float wa = g_dinv[sa];
        float2 ma = h[(size_t)sa * 32 + lane];
        acc.x += wa * ma.x; acc.y += wa * ma.y;
    }
    float2 bb = ((const float2*)b2)[lane];
    float2 r;
    r.x = fmaf(acc.x, di, bb.x);
    r.y = fmaf(acc.y, di, bb.y);
    ((float2*)out)[(size_t)w * 32 + lane] = r;
}

extern "C" void kernel_launch(void* const* d_in, const int* in_sizes, int n_in,
                              void* d_out, int out_size) {
    const float* x  = (const float*)d_in[0];
    const void*  ei = d_in[1];
    const float* W1 = (const float*)d_in[2];
    const float* b1 = (const float*)d_in[3];
    const float* W2 = (const float*)d_in[4];
    const float* b2 = (const float*)d_in[5];
    float* out = (float*)d_out;

    int n = in_sizes[0] / F1;      // 50000
    int E = in_sizes[1] / 2;       // 800000

    float *p_h1, *p_hr, *p_h2;
    int *p_cnt;
    cudaGetSymbolAddress((void**)&p_h1,  g_h1);
    cudaGetSymbolAddress((void**)&p_hr,  g_hr);
    cudaGetSymbolAddress((void**)&p_h2,  g_h2);
    cudaGetSymbolAddress((void**)&p_cnt, g_cnt);

    cudaMemsetAsync(p_cnt, 0, (size_t)n * sizeof(int));

    detect_kernel<<<1, 256>>>(ei, E);
    hist_kernel<<<(E + 255) / 256, 256>>>(ei, E);
    scan_kernel<<<1, 1024>>>(n);
    dinv_kernel<<<(n + 255) / 256, 256>>>(n);
    build_kernel<<<(E + 255) / 256, 256>>>(ei, E);

    // layer 1
    gemm_kernel<F1, 8><<<(n + 127) / 128, 256>>>(x, W1, p_h1, n);
    agg1_kernel<<<(n * 32 + 255) / 256, 256>>>(b1, n);

    // layer 2
    gemm_kernel<F2, 4><<<(n + 127) / 128, 256>>>(p_hr, W2, p_h2, n);
    agg2_kernel<<<(n * 32 + 255) / 256, 256>>>(b2, out, n);
}

// round 3
// speedup vs baseline: 1.7815x; 1.1782x over previous
#include <cuda_runtime.h>

#define MAX_N 50000
#define MAX_E 800000
#define F1 128
#define F2 64

// -------- scratch --------
__device__ float g_h1[MAX_N * F1];
__device__ float g_hr[MAX_N * F1];
__device__ float g_h2[MAX_N * F2];
__device__ float g_dinv[MAX_N];
__device__ int   g_cnt[MAX_N];
__device__ int   g_rowptr[MAX_N + 1];
__device__ int   g_cursor[MAX_N];
__device__ int   g_srcs[MAX_E];
__device__ int   g_is64;

// -------- dtype detection for edge_index (int64 vs int32) --------
__global__ void detect_kernel(const void* ei, int E) {
    __shared__ int bad;
    if (threadIdx.x == 0) bad = 0;
    __syncthreads();
    const long long* p = (const long long*)ei;
    int samples = E < 2048 ? E : 2048;
    for (int i = threadIdx.x; i < samples; i += blockDim.x) {
        long long v = p[i];
        if (v < 0 || v >= (long long)MAX_N) bad = 1;
    }
    __syncthreads();
    if (threadIdx.x == 0) g_is64 = bad ? 0 : 1;
}

__device__ __forceinline__ int edge_at(const void* ei, int idx) {
    if (g_is64) return (int)((const long long*)ei)[idx];
    return ((const int*)ei)[idx];
}

// -------- CSR construction --------
__global__ void hist_kernel(const void* ei, int E) {
    int e = blockIdx.x * blockDim.x + threadIdx.x;
    if (e >= E) return;
    atomicAdd(&g_cnt[edge_at(ei, E + e)], 1);
}

// single-block scan, 4 elems/thread; also emits cursor and dinv (deg = cnt+1)
__global__ void scan_kernel(int n) {
    __shared__ int warpsum[32];
    __shared__ int carrysh;
    int t = threadIdx.x, lane = t & 31, w = t >> 5;
    if (t == 0) carrysh = 0;
    __syncthreads();
    int nIter = (n + 4095) / 4096;
    for (int it = 0; it < nIter; it++) {
        int i0 = it * 4096 + t * 4;
        int4 v = make_int4(0, 0, 0, 0);
        if (i0 + 3 < n) v = *(const int4*)&g_cnt[i0];
        else {
            if (i0     < n) v.x = g_cnt[i0];
            if (i0 + 1 < n) v.y = g_cnt[i0 + 1];
            if (i0 + 2 < n) v.z = g_cnt[i0 + 2];
            if (i0 + 3 < n) v.w = g_cnt[i0 + 3];
        }
        int s = v.x + v.y + v.z + v.w;
        int x = s;
#pragma unroll
        for (int o = 1; o < 32; o <<= 1) {
            int y = __shfl_up_sync(~0u, x, o);
            if (lane >= o) x += y;
        }
        if (lane == 31) warpsum[w] = x;
        __syncthreads();
        if (w == 0) {
            int s2 = warpsum[lane];
#pragma unroll
            for (int o = 1; o < 32; o <<= 1) {
                int y = __shfl_up_sync(~0u, s2, o);
                if (lane >= o) s2 += y;
            }
            warpsum[lane] = s2;
        }
        __syncthreads();
        int wbase = w ? warpsum[w - 1] : 0;
        int e0 = carrysh + wbase + x - s;
        int e1 = e0 + v.x, e2 = e1 + v.y, e3 = e2 + v.z;
        if (i0 < n)     { g_rowptr[i0]     = e0; g_cursor[i0]     = e0; g_dinv[i0]     = rsqrtf((float)(v.x + 1)); }
        if (i0 + 1 < n) { g_rowptr[i0 + 1] = e1; g_cursor[i0 + 1] = e1; g_dinv[i0 + 1] = rsqrtf((float)(v.y + 1)); }
        if (i0 + 2 < n) { g_rowptr[i0 + 2] = e2; g_cursor[i0 + 2] = e2; g_dinv[i0 + 2] = rsqrtf((float)(v.z + 1)); }
        if (i0 + 3 < n) { g_rowptr[i0 + 3] = e3; g_cursor[i0 + 3] = e3; g_dinv[i0 + 3] = rsqrtf((float)(v.w + 1)); }
        __syncthreads();
        if (t == 0) carrysh += warpsum[31];
        __syncthreads();
    }
    if (t == 0) g_rowptr[n] = carrysh;
}

__global__ void build_kernel(const void* ei, int E) {
    int e = blockIdx.x * blockDim.x + threadIdx.x;
    if (e >= E) return;
    int s = edge_at(ei, e);
    int d = edge_at(ei, E + e);
    int pos = atomicAdd(&g_cursor[d], 1);
    g_srcs[pos] = s;
}

// -------- TF32 tensor-core GEMM: C[M,BN] = A[M,128] @ W[128,BN] --------
__device__ __forceinline__ float tf32r(float x) {
    unsigned u;
    asm("cvt.rna.tf32.f32 %0, %1;" : "=r"(u) : "f"(x));
    return __uint_as_float(u);
}

__device__ __forceinline__ void mma_tf32(float* c, unsigned a0, unsigned a1,
                                         unsigned a2, unsigned a3,
                                         unsigned b0, unsigned b1) {
    asm volatile(
        "mma.sync.aligned.m16n8k8.row.col.f32.tf32.tf32.f32 "
        "{%0,%1,%2,%3},{%4,%5,%6,%7},{%8,%9},{%0,%1,%2,%3};"
        : "+f"(c[0]), "+f"(c[1]), "+f"(c[2]), "+f"(c[3])
        : "r"(a0), "r"(a1), "r"(a2), "r"(a3), "r"(b0), "r"(b1));
}

template<int BN>
__global__ void __launch_bounds__(256) mma_gemm_kernel(
    const float* __restrict__ A, const float* __restrict__ W,
    float* __restrict__ C, int M) {
    constexpr int BM = 128, KC = 32, K = F1;
    constexpr int SAS = 40;        // sA row stride: 40 % 32 == 8 -> conflict-free frags
    constexpr int SBS = BN + 8;    // sB row stride: % 32 == 8 -> conflict-free frags
    constexpr int NT = BN / 8;
    __shared__ float sA[BM * SAS];
    __shared__ float sB[KC * SBS];

    int tid = threadIdx.x, lane = tid & 31, warp = tid >> 5;
    int g = lane >> 2, tig = lane & 3;
    int rowBase = blockIdx.x * BM;

    float c[NT][4];
#pragma unroll
    for (int nt = 0; nt < NT; nt++)
#pragma unroll
        for (int j = 0; j < 4; j++) c[nt][j] = 0.0f;

    for (int k0 = 0; k0 < K; k0 += KC) {
        // stage A tile (BM x KC), tf32-rounded
#pragma unroll
        for (int it = 0; it < BM * KC / 4 / 256; it++) {
            int idx = tid + it * 256;
            int r = idx >> 3;
            int cc = (idx & 7) * 4;
            int gr = rowBase + r;
            float4 v = make_float4(0.f, 0.f, 0.f, 0.f);
            if (gr < M) v = *(const float4*)&A[(size_t)gr * K + k0 + cc];
            sA[r * SAS + cc + 0] = tf32r(v.x);
            sA[r * SAS + cc + 1] = tf32r(v.y);
            sA[r * SAS + cc + 2] = tf32r(v.z);
            sA[r * SAS + cc + 3] = tf32r(v.w);
        }
        // stage W tile (KC x BN), tf32-rounded
#pragma unroll
        for (int it = 0; it < KC * BN / 4 / 256; it++) {
            int idx = tid + it * 256;
            int kk = idx / (BN / 4);
            int nn = (idx % (BN / 4)) * 4;
            float4 v = *(const float4*)&W[(size_t)(k0 + kk) * BN + nn];
            sB[kk * SBS + nn + 0] = tf32r(v.x);
            sB[kk * SBS + nn + 1] = tf32r(v.y);
            sB[kk * SBS + nn + 2] = tf32r(v.z);
            sB[kk * SBS + nn + 3] = tf32r(v.w);
        }
        __syncthreads();
#pragma unroll
        for (int ks = 0; ks < KC / 8; ks++) {
            int kk = ks * 8;
            int arow = warp * 16 + g;
            unsigned a0 = __float_as_uint(sA[arow * SAS + kk + tig]);
            unsigned a1 = __float_as_uint(sA[(arow + 8) * SAS + kk + tig]);
            unsigned a2 = __float_as_uint(sA[arow * SAS + kk + tig + 4]);
            unsigned a3 = __float_as_uint(sA[(arow + 8) * SAS + kk + tig + 4]);
#pragma unroll
            for (int nt = 0; nt < NT; nt++) {
                unsigned b0 = __float_as_uint(sB[(kk + tig) * SBS + nt * 8 + g]);
                unsigned b1 = __float_as_uint(sB[(kk + tig + 4) * SBS + nt * 8 + g]);
                mma_tf32(c[nt], a0, a1, a2, a3, b0, b1);
            }
        }
        __syncthreads();
    }
    int r0 = rowBase + warp * 16 + g;
    int r1 = r0 + 8;
#pragma unroll
    for (int nt = 0; nt < NT; nt++) {
        int col = nt * 8 + 2 * tig;
        if (r0 < M) *(float2*)&C[(size_t)r0 * BN + col] = make_float2(c[nt][0], c[nt][1]);
        if (r1 < M) *(float2*)&C[(size_t)r1 * BN + col] = make_float2(c[nt][2], c[nt][3]);
    }
}

// -------- aggregation layer 1: warp per node, fused self-loop + bias + relu --------
__global__ void agg1_kernel(const float* __restrict__ b1, int n) {
    int w    = (blockIdx.x * blockDim.x + threadIdx.x) >> 5;
    int lane = threadIdx.x & 31;
    if (w >= n) return;
    float di = g_dinv[w];
    const float4* h = (const float4*)g_h1;
    float4 v = h[(size_t)w * 32 + lane];
    float4 acc = make_float4(di * v.x, di * v.y, di * v.z, di * v.w);
    int j  = g_rowptr[w];
    int jE = g_rowptr[w + 1];
    for (; j + 1 < jE; j += 2) {
        int   sa = g_srcs[j],  sb = g_srcs[j + 1];
        float wa = g_dinv[sa], wb = g_dinv[sb];
        float4 ma = h[(size_t)sa * 32 + lane];
        float4 mb = h[(size_t)sb * 32 + lane];
        acc.x += wa * ma.x + wb * mb.x;
        acc.y += wa * ma.y + wb * mb.y;
        acc.z += wa * ma.z + wb * mb.z;
        acc.w += wa * ma.w + wb * mb.w;
    }
    if (j < jE) {
        int   sa = g_srcs[j];
        float wa = g_dinv[sa];
        float4 ma = h[(size_t)sa * 32 + lane];
        acc.x += wa * ma.x; acc.y += wa * ma.y;
        acc.z += wa * ma.z; acc.w += wa * ma.w;
    }
    float4 bb = ((const float4*)b1)[lane];
    float4 r;
    r.x = fmaxf(fmaf(acc.x, di, bb.x), 0.0f);
    r.y = fmaxf(fmaf(acc.y, di, bb.y), 0.0f);
    r.z = fmaxf(fmaf(acc.z, di, bb.z), 0.0f);
    r.w = fmaxf(fmaf(acc.w, di, bb.w), 0.0f);
    ((float4*)g_hr)[(size_t)w * 32 + lane] = r;
}

// -------- aggregation layer 2: warp per node, fused self-loop + bias --------
__global__ void agg2_kernel(const float* __restrict__ b2, float* __restrict__ out, int n) {
    int w    = (blockIdx.x * blockDim.x + threadIdx.x) >> 5;
    int lane = threadIdx.x & 31;
    if (w >= n) return;
    float di = g_dinv[w];
    const float2* h = (const float2*)g_h2;
    float2 v = h[(size_t)w * 32 + lane];
    float2 acc = make_float2(di * v.x, di * v.y);
    int j  = g_rowptr[w];
    int jE = g_rowptr[w + 1];
    for (; j + 1 < jE; j += 2) {
        int   sa = g_srcs[j],  sb = g_srcs[j + 1];
        float wa = g_dinv[sa], wb = g_dinv[sb];
        float2 ma = h[(size_t)sa * 32 + lane];
        float2 mb = h[(size_t)sb * 32 + lane];
        acc.x += wa * ma.x + wb * mb.x;
        acc.y += wa * ma.y + wb * mb.y;
    }
    if (j < jE) {
        int   sa = g_srcs[j];
        float wa = g_dinv[sa];
        float2 ma = h[(size_t)sa * 32 + lane];
        acc.x += wa * ma.x; acc.y += wa * ma.y;
    }
    float2 bb = ((const float2*)b2)[lane];
    float2 r;
    r.x = fmaf(acc.x, di, bb.x);
    r.y = fmaf(acc.y, di, bb.y);
    ((float2*)out)[(size_t)w * 32 + lane] = r;
}

extern "C" void kernel_launch(void* const* d_in, const int* in_sizes, int n_in,
                              void* d_out, int out_size) {
    const float* x  = (const float*)d_in[0];
    const void*  ei = d_in[1];
    const float* W1 = (const float*)d_in[2];
    const float* b1 = (const float*)d_in[3];
    const float* W2 = (const float*)d_in[4];
    const float* b2 = (const float*)d_in[5];
    float* out = (float*)d_out;

    int n = in_sizes[0] / F1;      // 50000
    int E = in_sizes[1] / 2;       // 800000

    float *p_h1, *p_hr, *p_h2;
    int *p_cnt;
    cudaGetSymbolAddress((void**)&p_h1,  g_h1);
    cudaGetSymbolAddress((void**)&p_hr,  g_hr);
    cudaGetSymbolAddress((void**)&p_h2,  g_h2);
    cudaGetSymbolAddress((void**)&p_cnt, g_cnt);

    cudaMemsetAsync(p_cnt, 0, (size_t)n * sizeof(int));

    detect_kernel<<<1, 256>>>(ei, E);
    hist_kernel<<<(E + 255) / 256, 256>>>(ei, E);
    scan_kernel<<<1, 1024>>>(n);
    build_kernel<<<(E + 255) / 256, 256>>>(ei, E);

    // layer 1
    mma_gemm_kernel<F1><<<(n + 127) / 128, 256>>>(x, W1, p_h1, n);
    agg1_kernel<<<(n * 32 + 255) / 256, 256>>>(b1, n);

    // layer 2
    mma_gemm_kernel<F2><<<(n + 127) / 128, 256>>>(p_hr, W2, p_h2, n);
    agg2_kernel<<<(n * 32 + 255) / 256, 256>>>(b2, out, n);
}

// round 4
// speedup vs baseline: 1.9889x; 1.1165x over previous
#include <cuda_runtime.h>
#include <cuda_fp16.h>

#define MAX_N 50000
#define MAX_E 800000
#define F1 128
#define F2 64

// -------- scratch --------
__device__ uint2 g_h1h[MAX_N * 32];   // h1 = x@W1 in fp16: 128 halves/row = 32 uint2
__device__ float g_hr[MAX_N * F1];    // relu(agg1 + self + b1), fp32 (GEMM2 input)
__device__ uint  g_h2h[MAX_N * 32];   // h2 = hr@W2 in fp16: 64 halves/row = 32 uint
__device__ float g_dinv[MAX_N];
__device__ int   g_cnt[MAX_N];
__device__ int   g_rowptr[MAX_N + 1];
__device__ int   g_cursor[MAX_N];
__device__ int   g_srcs[MAX_E];
__device__ int   g_is64;

// -------- detect edge dtype (int64 vs int32) + zero histogram --------
__global__ void detect_zero_kernel(const void* ei, int E, int n) {
    int i = blockIdx.x * blockDim.x + threadIdx.x;
    if (i < n) g_cnt[i] = 0;
    if (blockIdx.x == 0) {
        __shared__ int bad;
        if (threadIdx.x == 0) bad = 0;
        __syncthreads();
        const long long* p = (const long long*)ei;
        int samples = E < 2048 ? E : 2048;
        for (int k = threadIdx.x; k < samples; k += blockDim.x) {
            long long v = p[k];
            if (v < 0 || v >= (long long)MAX_N) bad = 1;
        }
        __syncthreads();
        if (threadIdx.x == 0) g_is64 = bad ? 0 : 1;
    }
}

__device__ __forceinline__ int edge_at(const void* ei, int idx) {
    if (g_is64) return (int)((const long long*)ei)[idx];
    return ((const int*)ei)[idx];
}

// -------- TF32 mma helpers --------
__device__ __forceinline__ float tf32r(float x) {
    unsigned u;
    asm("cvt.rna.tf32.f32 %0, %1;" : "=r"(u) : "f"(x));
    return __uint_as_float(u);
}

__device__ __forceinline__ void mma_tf32(float* c, unsigned a0, unsigned a1,
                                         unsigned a2, unsigned a3,
                                         unsigned b0, unsigned b1) {
    asm volatile(
        "mma.sync.aligned.m16n8k8.row.col.f32.tf32.tf32.f32 "
        "{%0,%1,%2,%3},{%4,%5,%6,%7},{%8,%9},{%0,%1,%2,%3};"
        : "+f"(c[0]), "+f"(c[1]), "+f"(c[2]), "+f"(c[3])
        : "r"(a0), "r"(a1), "r"(a2), "r"(a3), "r"(b0), "r"(b1));
}

// C[M,BN] = A[M,128] @ W[128,BN], fp16 output. One block = 128 rows.
template<int BN>
__device__ __forceinline__ void gemm_body(const float* __restrict__ A,
                                          const float* __restrict__ W,
                                          __half* __restrict__ C, int M, int blk) {
    constexpr int BM = 128, KC = 32, K = F1;
    constexpr int SAS = 40;       // 40 % 32 == 8 -> conflict-free fragment reads
    constexpr int SBS = BN + 8;
    constexpr int NT = BN / 8;
    __shared__ float sA[BM * SAS];
    __shared__ float sB[KC * SBS];

    int tid = threadIdx.x, lane = tid & 31, warp = tid >> 5;
    int g = lane >> 2, tig = lane & 3;
    int rowBase = blk * BM;

    float c[NT][4];
#pragma unroll
    for (int nt = 0; nt < NT; nt++)
#pragma unroll
        for (int j = 0; j < 4; j++) c[nt][j] = 0.0f;

    for (int k0 = 0; k0 < K; k0 += KC) {
#pragma unroll
        for (int it = 0; it < BM * KC / 4 / 256; it++) {
            int idx = tid + it * 256;
            int r = idx >> 3;
            int cc = (idx & 7) * 4;
            int gr = rowBase + r;
            float4 v = make_float4(0.f, 0.f, 0.f, 0.f);
            if (gr < M) v = *(const float4*)&A[(size_t)gr * K + k0 + cc];
            sA[r * SAS + cc + 0] = tf32r(v.x);
            sA[r * SAS + cc + 1] = tf32r(v.y);
            sA[r * SAS + cc + 2] = tf32r(v.z);
            sA[r * SAS + cc + 3] = tf32r(v.w);
        }
#pragma unroll
        for (int it = 0; it < KC * BN / 4 / 256; it++) {
            int idx = tid + it * 256;
            int kk = idx / (BN / 4);
            int nn = (idx % (BN / 4)) * 4;
            float4 v = *(const float4*)&W[(size_t)(k0 + kk) * BN + nn];
            sB[kk * SBS + nn + 0] = tf32r(v.x);
            sB[kk * SBS + nn + 1] = tf32r(v.y);
            sB[kk * SBS + nn + 2] = tf32r(v.z);
            sB[kk * SBS + nn + 3] = tf32r(v.w);
        }
        __syncthreads();
#pragma unroll
        for (int ks = 0; ks < KC / 8; ks++) {
            int kk = ks * 8;
            int arow = warp * 16 + g;
            unsigned a0 = __float_as_uint(sA[arow * SAS + kk + tig]);
            unsigned a1 = __float_as_uint(sA[(arow + 8) * SAS + kk + tig]);
            unsigned a2 = __float_as_uint(sA[arow * SAS + kk + tig + 4]);
            unsigned a3 = __float_as_uint(sA[(arow + 8) * SAS + kk + tig + 4]);
#pragma unroll
            for (int nt = 0; nt < NT; nt++) {
                unsigned b0 = __float_as_uint(sB[(kk + tig) * SBS + nt * 8 + g]);
                unsigned b1 = __float_as_uint(sB[(kk + tig + 4) * SBS + nt * 8 + g]);
                mma_tf32(c[nt], a0, a1, a2, a3, b0, b1);
            }
        }
        __syncthreads();
    }
    int r0 = rowBase + warp * 16 + g;
    int r1 = r0 + 8;
#pragma unroll
    for (int nt = 0; nt < NT; nt++) {
        int col = nt * 8 + 2 * tig;
        if (r0 < M) *(__half2*)&C[(size_t)r0 * BN + col] = __floats2half2_rn(c[nt][0], c[nt][1]);
        if (r1 < M) *(__half2*)&C[(size_t)r1 * BN + col] = __floats2half2_rn(c[nt][2], c[nt][3]);
    }
}

// -------- fused: GEMM1 (blocks [0,Gg)) + histogram (blocks [Gg, ...)) --------
__global__ void __launch_bounds__(256) fused_gemm1_hist_kernel(
    const float* __restrict__ A, const float* __restrict__ W,
    __half* __restrict__ C, int M, const void* ei, int E, int Gg) {
    if ((int)blockIdx.x < Gg) {
        gemm_body<F1>(A, W, C, M, blockIdx.x);
    } else {
        int idx = ((int)blockIdx.x - Gg) * 256 + threadIdx.x;
        int e0 = idx * 2, e1 = idx * 2 + 1;
        if (e0 < E) atomicAdd(&g_cnt[edge_at(ei, E + e0)], 1);
        if (e1 < E) atomicAdd(&g_cnt[edge_at(ei, E + e1)], 1);
    }
}

// -------- single-block scan (4/thread): rowptr, cursor, dinv --------
__global__ void scan_kernel(int n) {
    __shared__ int warpsum[32];
    __shared__ int carrysh;
    int t = threadIdx.x, lane = t & 31, w = t >> 5;
    if (t == 0) carrysh = 0;
    __syncthreads();
    int nIter = (n + 4095) / 4096;
    for (int it = 0; it < nIter; it++) {
        int i0 = it * 4096 + t * 4;
        int4 v = make_int4(0, 0, 0, 0);
        if (i0 + 3 < n) v = *(const int4*)&g_cnt[i0];
        else {
            if (i0     < n) v.x = g_cnt[i0];
            if (i0 + 1 < n) v.y = g_cnt[i0 + 1];
            if (i0 + 2 < n) v.z = g_cnt[i0 + 2];
            if (i0 + 3 < n) v.w = g_cnt[i0 + 3];
        }
        int s = v.x + v.y + v.z + v.w;
        int x = s;
#pragma unroll
        for (int o = 1; o < 32; o <<= 1) {
            int y = __shfl_up_sync(~0u, x, o);
            if (lane >= o) x += y;
        }
        if (lane == 31) warpsum[w] = x;
        __syncthreads();
        if (w == 0) {
            int s2 = warpsum[lane];
#pragma unroll
            for (int o = 1; o < 32; o <<= 1) {
                int y = __shfl_up_sync(~0u, s2, o);
                if (lane >= o) s2 += y;
            }
            warpsum[lane] = s2;
        }
        __syncthreads();
        int wbase = w ? warpsum[w - 1] : 0;
        int e0 = carrysh + wbase + x - s;
        int e1 = e0 + v.x, e2 = e1 + v.y, e3 = e2 + v.z;
        if (i0 < n)     { g_rowptr[i0]     = e0; g_cursor[i0]     = e0; g_dinv[i0]     = rsqrtf((float)(v.x + 1)); }
        if (i0 + 1 < n) { g_rowptr[i0 + 1] = e1; g_cursor[i0 + 1] = e1; g_dinv[i0 + 1] = rsqrtf((float)(v.y + 1)); }
        if (i0 + 2 < n) { g_rowptr[i0 + 2] = e2; g_cursor[i0 + 2] = e2; g_dinv[i0 + 2] = rsqrtf((float)(v.z + 1)); }
        if (i0 + 3 < n) { g_rowptr[i0 + 3] = e3; g_cursor[i0 + 3] = e3; g_dinv[i0 + 3] = rsqrtf((float)(v.w + 1)); }
        __syncthreads();
        if (t == 0) carrysh += warpsum[31];
        __syncthreads();
    }
    if (t == 0) g_rowptr[n] = carrysh;
}

// -------- CSR fill: 2 edges/thread for atomic MLP --------
__global__ void build_kernel(const void* ei, int E) {
    int idx = blockIdx.x * blockDim.x + threadIdx.x;
    int e0 = idx * 2, e1 = e0 + 1;
    if (e0 >= E) return;
    int s0 = edge_at(ei, e0);
    int d0 = edge_at(ei, E + e0);
    int s1 = 0, d1 = -1;
    if (e1 < E) { s1 = edge_at(ei, e1); d1 = edge_at(ei, E + e1); }
    int p0 = atomicAdd(&g_cursor[d0], 1);
    int p1 = (d1 >= 0) ? atomicAdd(&g_cursor[d1], 1) : -1;
    g_srcs[p0] = s0;
    if (p1 >= 0) g_srcs[p1] = s1;
}

// -------- agg layer 1: warp/node, fp16 gathers, fused self+bias+relu --------
__global__ void agg1_kernel(const float* __restrict__ b1, int n) {
    int w    = (blockIdx.x * blockDim.x + threadIdx.x) >> 5;
    int lane = threadIdx.x & 31;
    if (w >= n) return;
    float di = g_dinv[w];
    uint2 uself = g_h1h[(size_t)w * 32 + lane];
    float2 s0 = __half22float2(*(__half2*)&uself.x);
    float2 s1 = __half22float2(*(__half2*)&uself.y);
    float4 acc = make_float4(di * s0.x, di * s0.y, di * s1.x, di * s1.y);
    int j  = g_rowptr[w];
    int jE = g_rowptr[w + 1];
    for (; j + 1 < jE; j += 2) {
        int   sa = g_srcs[j],  sb = g_srcs[j + 1];
        float wa = g_dinv[sa], wb = g_dinv[sb];
        uint2 ua = g_h1h[(size_t)sa * 32 + lane];
        uint2 ub = g_h1h[(size_t)sb * 32 + lane];
        float2 a0 = __half22float2(*(__half2*)&ua.x);
        float2 a1 = __half22float2(*(__half2*)&ua.y);
        float2 c0 = __half22float2(*(__half2*)&ub.x);
        float2 c1 = __half22float2(*(__half2*)&ub.y);
        acc.x += wa * a0.x + wb * c0.x;
        acc.y += wa * a0.y + wb * c0.y;
        acc.z += wa * a1.x + wb * c1.x;
        acc.w += wa * a1.y + wb * c1.y;
    }
    if (j < jE) {
        int   sa = g_srcs[j];
        float wa = g_dinv[sa];
        uint2 ua = g_h1h[(size_t)sa * 32 + lane];
        float2 a0 = __half22float2(*(__half2*)&ua.x);
        float2 a1 = __half22float2(*(__half2*)&ua.y);
        acc.x += wa * a0.x; acc.y += wa * a0.y;
        acc.z += wa * a1.x; acc.w += wa * a1.y;
    }
    float4 bb = ((const float4*)b1)[lane];
    float4 r;
    r.x = fmaxf(fmaf(acc.x, di, bb.x), 0.0f);
    r.y = fmaxf(fmaf(acc.y, di, bb.y), 0.0f);
    r.z = fmaxf(fmaf(acc.z, di, bb.z), 0.0f);
    r.w = fmaxf(fmaf(acc.w, di, bb.w), 0.0f);
    ((float4*)g_hr)[(size_t)w * 32 + lane] = r;
}

// -------- agg layer 2: warp/node, fp16 gathers, fused self+bias --------
__global__ void agg2_kernel(const float* __restrict__ b2, float* __restrict__ out, int n) {
    int w    = (blockIdx.x * blockDim.x + threadIdx.x) >> 5;
    int lane = threadIdx.x & 31;
    if (w >= n) return;
    float di = g_dinv[w];
    uint uself = g_h2h[(size_t)w * 32 + lane];
    float2 sv = __half22float2(*(__half2*)&uself);
    float2 acc = make_float2(di * sv.x, di * sv.y);
    int j  = g_rowptr[w];
    int jE = g_rowptr[w + 1];
    for (; j + 1 < jE; j += 2) {
        int   sa = g_srcs[j],  sb = g_srcs[j + 1];
        float wa = g_dinv[sa], wb = g_dinv[sb];
        uint ua = g_h2h[(size_t)sa * 32 + lane];
        uint ub = g_h2h[(size_t)sb * 32 + lane];
        float2 fa = __half22float2(*(__half2*)&ua);
        float2 fb = __half22float2(*(__half2*)&ub);
        acc.x += wa * fa.x + wb * fb.x;
        acc.y += wa * fa.y + wb * fb.y;
    }
    if (j < jE) {
        int   sa = g_srcs[j];
        float wa = g_dinv[sa];
        uint ua = g_h2h[(size_t)sa * 32 + lane];
        float2 fa = __half22float2(*(__half2*)&ua);
        acc.x += wa * fa.x; acc.y += wa * fa.y;
    }
    float2 bb = ((const float2*)b2)[lane];
    float2 r;
    r.x = fmaf(acc.x, di, bb.x);
    r.y = fmaf(acc.y, di, bb.y);
    ((float2*)out)[(size_t)w * 32 + lane] = r;
}

// -------- standalone GEMM2 --------
__global__ void __launch_bounds__(256) gemm2_kernel(
    const float* __restrict__ A, const float* __restrict__ W,
    __half* __restrict__ C, int M) {
    gemm_body<F2>(A, W, C, M, blockIdx.x);
}

extern "C" void kernel_launch(void* const* d_in, const int* in_sizes, int n_in,
                              void* d_out, int out_size) {
    const float* x  = (const float*)d_in[0];
    const void*  ei = d_in[1];
    const float* W1 = (const float*)d_in[2];
    const float* b1 = (const float*)d_in[3];
    const float* W2 = (const float*)d_in[4];
    const float* b2 = (const float*)d_in[5];
    float* out = (float*)d_out;

    int n = in_sizes[0] / F1;      // 50000
    int E = in_sizes[1] / 2;       // 800000

    void *p_h1h, *p_hr, *p_h2h;
    cudaGetSymbolAddress(&p_h1h, g_h1h);
    cudaGetSymbolAddress(&p_hr,  g_hr);
    cudaGetSymbolAddress(&p_h2h, g_h2h);

    detect_zero_kernel<<<(n + 255) / 256, 256>>>(ei, E, n);

    int Gg = (n + 127) / 128;                 // GEMM1 blocks
    int Gh = (E + 511) / 512;                 // hist blocks (2 edges/thread)
    fused_gemm1_hist_kernel<<<Gg + Gh, 256>>>(x, W1, (__half*)p_h1h, n, ei, E, Gg);

    scan_kernel<<<1, 1024>>>(n);
    build_kernel<<<(E + 511) / 512, 256>>>(ei, E);

    agg1_kernel<<<(n * 32 + 255) / 256, 256>>>(b1, n);
    gemm2_kernel<<<(n + 127) / 128, 256>>>((const float*)p_hr, W2, (__half*)p_h2h, n);
    agg2_kernel<<<(n * 32 + 255) / 256, 256>>>(b2, out, n);
}

// round 5
// speedup vs baseline: 2.0156x; 1.0134x over previous
#include <cuda_runtime.h>
#include <cuda_fp16.h>

#define MAX_N 50000
#define MAX_E 800000
#define F1 128
#define F2 64

// -------- scratch --------
__device__ uint2 g_h1h[MAX_N * 32];   // h1 fp16: 128 halves/row
__device__ uint2 g_hrh[MAX_N * 32];   // relu(agg1) fp16: 128 halves/row
__device__ uint  g_h2h[MAX_N * 32];   // h2 fp16: 64 halves/row
__device__ float g_dinv[MAX_N];
__device__ int   g_cnt[MAX_N];
__device__ int   g_rowptr[MAX_N + 1];
__device__ int   g_cursor[MAX_N];
__device__ int   g_srcs[MAX_E];
__device__ int   g_is64;

// -------- detect edge dtype (int64 vs int32) + zero histogram --------
__global__ void detect_zero_kernel(const void* ei, int E, int n) {
    int i = blockIdx.x * blockDim.x + threadIdx.x;
    if (i < n) g_cnt[i] = 0;
    if (blockIdx.x == 0) {
        __shared__ int bad;
        if (threadIdx.x == 0) bad = 0;
        __syncthreads();
        const long long* p = (const long long*)ei;
        int samples = E < 2048 ? E : 2048;
        for (int k = threadIdx.x; k < samples; k += blockDim.x) {
            long long v = p[k];
            if (v < 0 || v >= (long long)MAX_N) bad = 1;
        }
        __syncthreads();
        if (threadIdx.x == 0) g_is64 = bad ? 0 : 1;
    }
}

__device__ __forceinline__ int edge_at(const void* ei, int idx) {
    if (g_is64) return (int)((const long long*)ei)[idx];
    return ((const int*)ei)[idx];
}

// -------- histogram: 4 edges/thread, vectorized int32 path --------
__global__ void hist_kernel(const void* ei, int E) {
    int idx = blockIdx.x * blockDim.x + threadIdx.x;
    int base = idx * 4;
    if (base >= E) return;
    if (!g_is64 && base + 3 < E) {
        const int* dp = (const int*)ei + E;
        int4 d = *(const int4*)(dp + base);   // E assumed %4==0 handled by caller grid
        atomicAdd(&g_cnt[d.x], 1);
        atomicAdd(&g_cnt[d.y], 1);
        atomicAdd(&g_cnt[d.z], 1);
        atomicAdd(&g_cnt[d.w], 1);
    } else {
#pragma unroll
        for (int q = 0; q < 4; q++) {
            int e = base + q;
            if (e < E) atomicAdd(&g_cnt[edge_at(ei, E + e)], 1);
        }
    }
}

// -------- single-block scan (4/thread): rowptr, cursor, dinv --------
__global__ void scan_kernel(int n) {
    __shared__ int warpsum[32];
    __shared__ int carrysh;
    int t = threadIdx.x, lane = t & 31, w = t >> 5;
    if (t == 0) carrysh = 0;
    __syncthreads();
    int nIter = (n + 4095) / 4096;
    for (int it = 0; it < nIter; it++) {
        int i0 = it * 4096 + t * 4;
        int4 v = make_int4(0, 0, 0, 0);
        if (i0 + 3 < n) v = *(const int4*)&g_cnt[i0];
        else {
            if (i0     < n) v.x = g_cnt[i0];
            if (i0 + 1 < n) v.y = g_cnt[i0 + 1];
            if (i0 + 2 < n) v.z = g_cnt[i0 + 2];
            if (i0 + 3 < n) v.w = g_cnt[i0 + 3];
        }
        int s = v.x + v.y + v.z + v.w;
        int x = s;
#pragma unroll
        for (int o = 1; o < 32; o <<= 1) {
            int y = __shfl_up_sync(~0u, x, o);
            if (lane >= o) x += y;
        }
        if (lane == 31) warpsum[w] = x;
        __syncthreads();
        if (w == 0) {
            int s2 = warpsum[lane];
#pragma unroll
            for (int o = 1; o < 32; o <<= 1) {
                int y = __shfl_up_sync(~0u, s2, o);
                if (lane >= o) s2 += y;
            }
            warpsum[lane] = s2;
        }
        __syncthreads();
        int wbase = w ? warpsum[w - 1] : 0;
        int e0 = carrysh + wbase + x - s;
        int e1 = e0 + v.x, e2 = e1 + v.y, e3 = e2 + v.z;
        if (i0 < n)     { g_rowptr[i0]     = e0; g_cursor[i0]     = e0; g_dinv[i0]     = rsqrtf((float)(v.x + 1)); }
        if (i0 + 1 < n) { g_rowptr[i0 + 1] = e1; g_cursor[i0 + 1] = e1; g_dinv[i0 + 1] = rsqrtf((float)(v.y + 1)); }
        if (i0 + 2 < n) { g_rowptr[i0 + 2] = e2; g_cursor[i0 + 2] = e2; g_dinv[i0 + 2] = rsqrtf((float)(v.z + 1)); }
        if (i0 + 3 < n) { g_rowptr[i0 + 3] = e3; g_cursor[i0 + 3] = e3; g_dinv[i0 + 3] = rsqrtf((float)(v.w + 1)); }
        __syncthreads();
        if (t == 0) carrysh += warpsum[31];
        __syncthreads();
    }
    if (t == 0) g_rowptr[n] = carrysh;
}

// -------- TF32 mma helpers --------
__device__ __forceinline__ float tf32r(float x) {
    unsigned u;
    asm("cvt.rna.tf32.f32 %0, %1;" : "=r"(u) : "f"(x));
    return __uint_as_float(u);
}

__device__ __forceinline__ void mma_tf32(float* c, unsigned a0, unsigned a1,
                                         unsigned a2, unsigned a3,
                                         unsigned b0, unsigned b1) {
    asm volatile(
        "mma.sync.aligned.m16n8k8.row.col.f32.tf32.tf32.f32 "
        "{%0,%1,%2,%3},{%4,%5,%6,%7},{%8,%9},{%0,%1,%2,%3};"
        : "+f"(c[0]), "+f"(c[1]), "+f"(c[2]), "+f"(c[3])
        : "r"(a0), "r"(a1), "r"(a2), "r"(a3), "r"(b0), "r"(b1));
}

__device__ __forceinline__ float4 loadA4(const float* A, size_t off) {
    return *(const float4*)(A + off);
}
__device__ __forceinline__ float4 loadA4(const __half* A, size_t off) {
    uint2 u = *(const uint2*)(A + off);
    float2 f0 = __half22float2(*(__half2*)&u.x);
    float2 f1 = __half22float2(*(__half2*)&u.y);
    return make_float4(f0.x, f0.y, f1.x, f1.y);
}

// C[M,BN] = A[M,128] @ W[128,BN], fp16 output. One block = 128 rows.
template<int BN, typename TA>
__device__ __forceinline__ void gemm_body(const TA* __restrict__ A,
                                          const float* __restrict__ W,
                                          __half* __restrict__ C, int M, int blk) {
    constexpr int BM = 128, KC = 32, K = F1;
    constexpr int SAS = 40;       // 40 % 32 == 8 -> conflict-free fragment reads
    constexpr int SBS = BN + 8;
    constexpr int NT = BN / 8;
    __shared__ float sA[BM * SAS];
    __shared__ float sB[KC * SBS];

    int tid = threadIdx.x, lane = tid & 31, warp = tid >> 5;
    int g = lane >> 2, tig = lane & 3;
    int rowBase = blk * BM;

    float c[NT][4];
#pragma unroll
    for (int nt = 0; nt < NT; nt++)
#pragma unroll
        for (int j = 0; j < 4; j++) c[nt][j] = 0.0f;

    for (int k0 = 0; k0 < K; k0 += KC) {
#pragma unroll
        for (int it = 0; it < BM * KC / 4 / 256; it++) {
            int idx = tid + it * 256;
            int r = idx >> 3;
            int cc = (idx & 7) * 4;
            int gr = rowBase + r;
            float4 v = make_float4(0.f, 0.f, 0.f, 0.f);
            if (gr < M) v = loadA4(A, (size_t)gr * K + k0 + cc);
            sA[r * SAS + cc + 0] = tf32r(v.x);
            sA[r * SAS + cc + 1] = tf32r(v.y);
            sA[r * SAS + cc + 2] = tf32r(v.z);
            sA[r * SAS + cc + 3] = tf32r(v.w);
        }
#pragma unroll
        for (int it = 0; it < KC * BN / 4 / 256; it++) {
            int idx = tid + it * 256;
            int kk = idx / (BN / 4);
            int nn = (idx % (BN / 4)) * 4;
            float4 v = *(const float4*)&W[(size_t)(k0 + kk) * BN + nn];
            sB[kk * SBS + nn + 0] = tf32r(v.x);
            sB[kk * SBS + nn + 1] = tf32r(v.y);
            sB[kk * SBS + nn + 2] = tf32r(v.z);
            sB[kk * SBS + nn + 3] = tf32r(v.w);
        }
        __syncthreads();
#pragma unroll
        for (int ks = 0; ks < KC / 8; ks++) {
            int kk = ks * 8;
            int arow = warp * 16 + g;
            unsigned a0 = __float_as_uint(sA[arow * SAS + kk + tig]);
            unsigned a1 = __float_as_uint(sA[(arow + 8) * SAS + kk + tig]);
            unsigned a2 = __float_as_uint(sA[arow * SAS + kk + tig + 4]);
            unsigned a3 = __float_as_uint(sA[(arow + 8) * SAS + kk + tig + 4]);
#pragma unroll
            for (int nt = 0; nt < NT; nt++) {
                unsigned b0 = __float_as_uint(sB[(kk + tig) * SBS + nt * 8 + g]);
                unsigned b1 = __float_as_uint(sB[(kk + tig + 4) * SBS + nt * 8 + g]);
                mma_tf32(c[nt], a0, a1, a2, a3, b0, b1);
            }
        }
        __syncthreads();
    }
    int r0 = rowBase + warp * 16 + g;
    int r1 = r0 + 8;
#pragma unroll
    for (int nt = 0; nt < NT; nt++) {
        int col = nt * 8 + 2 * tig;
        if (r0 < M) *(__half2*)&C[(size_t)r0 * BN + col] = __floats2half2_rn(c[nt][0], c[nt][1]);
        if (r1 < M) *(__half2*)&C[(size_t)r1 * BN + col] = __floats2half2_rn(c[nt][2], c[nt][3]);
    }
}

// -------- fused: GEMM1 (blocks [0,Gg)) + CSR build (blocks [Gg,...)) --------
__global__ void __launch_bounds__(256) fused_gemm1_build_kernel(
    const float* __restrict__ A, const float* __restrict__ W,
    __half* __restrict__ C, int M, const void* ei, int E, int Gg) {
    if ((int)blockIdx.x < Gg) {
        gemm_body<F1>(A, W, C, M, blockIdx.x);
        return;
    }
    int idx = ((int)blockIdx.x - Gg) * 256 + threadIdx.x;
    int base = idx * 4;
    if (base >= E) return;
    if (!g_is64 && base + 3 < E) {
        const int* sp = (const int*)ei;
        int4 s = *(const int4*)(sp + base);
        int4 d = *(const int4*)(sp + E + base);
        int p0 = atomicAdd(&g_cursor[d.x], 1);
        int p1 = atomicAdd(&g_cursor[d.y], 1);
        int p2 = atomicAdd(&g_cursor[d.z], 1);
        int p3 = atomicAdd(&g_cursor[d.w], 1);
        g_srcs[p0] = s.x; g_srcs[p1] = s.y;
        g_srcs[p2] = s.z; g_srcs[p3] = s.w;
    } else {
#pragma unroll
        for (int q = 0; q < 4; q++) {
            int e = base + q;
            if (e < E) {
                int s = edge_at(ei, e);
                int d = edge_at(ei, E + e);
                g_srcs[atomicAdd(&g_cursor[d], 1)] = s;
            }
        }
    }
}

// -------- agg layer 1: warp/node, fp16 gathers, 4-way MLP, fused self+bias+relu --------
__global__ void agg1_kernel(const float* __restrict__ b1, int n) {
    int w    = (blockIdx.x * blockDim.x + threadIdx.x) >> 5;
    int lane = threadIdx.x & 31;
    if (w >= n) return;
    float di = g_dinv[w];
    uint2 uself = g_h1h[(size_t)w * 32 + lane];
    float2 s0 = __half22float2(*(__half2*)&uself.x);
    float2 s1 = __half22float2(*(__half2*)&uself.y);
    float4 acc = make_float4(di * s0.x, di * s0.y, di * s1.x, di * s1.y);
    int j  = g_rowptr[w];
    int jE = g_rowptr[w + 1];
    for (; j + 3 < jE; j += 4) {
        int i0 = g_srcs[j], i1 = g_srcs[j + 1], i2 = g_srcs[j + 2], i3 = g_srcs[j + 3];
        float w0 = g_dinv[i0], w1 = g_dinv[i1], w2 = g_dinv[i2], w3 = g_dinv[i3];
        uint2 u0 = g_h1h[(size_t)i0 * 32 + lane];
        uint2 u1 = g_h1h[(size_t)i1 * 32 + lane];
        uint2 u2 = g_h1h[(size_t)i2 * 32 + lane];
        uint2 u3 = g_h1h[(size_t)i3 * 32 + lane];
        float2 a0 = __half22float2(*(__half2*)&u0.x), a1 = __half22float2(*(__half2*)&u0.y);
        float2 c0 = __half22float2(*(__half2*)&u1.x), c1 = __half22float2(*(__half2*)&u1.y);
        float2 d0 = __half22float2(*(__half2*)&u2.x), d1 = __half22float2(*(__half2*)&u2.y);
        float2 e0 = __half22float2(*(__half2*)&u3.x), e1 = __half22float2(*(__half2*)&u3.y);
        acc.x += w0 * a0.x + w1 * c0.x + w2 * d0.x + w3 * e0.x;
        acc.y += w0 * a0.y + w1 * c0.y + w2 * d0.y + w3 * e0.y;
        acc.z += w0 * a1.x + w1 * c1.x + w2 * d1.x + w3 * e1.x;
        acc.w += w0 * a1.y + w1 * c1.y + w2 * d1.y + w3 * e1.y;
    }
    for (; j < jE; j++) {
        int   sa = g_srcs[j];
        float wa = g_dinv[sa];
        uint2 ua = g_h1h[(size_t)sa * 32 + lane];
        float2 a0 = __half22float2(*(__half2*)&ua.x);
        float2 a1 = __half22float2(*(__half2*)&ua.y);
        acc.x += wa * a0.x; acc.y += wa * a0.y;
        acc.z += wa * a1.x; acc.w += wa * a1.y;
    }
    float4 bb = ((const float4*)b1)[lane];
    float rx = fmaxf(fmaf(acc.x, di, bb.x), 0.0f);
    float ry = fmaxf(fmaf(acc.y, di, bb.y), 0.0f);
    float rz = fmaxf(fmaf(acc.z, di, bb.z), 0.0f);
    float rw = fmaxf(fmaf(acc.w, di, bb.w), 0.0f);
    uint2 o;
    *(__half2*)&o.x = __floats2half2_rn(rx, ry);
    *(__half2*)&o.y = __floats2half2_rn(rz, rw);
    g_hrh[(size_t)w * 32 + lane] = o;
}

// -------- agg layer 2: warp/node, fp16 gathers, 4-way MLP, fused self+bias --------
__global__ void agg2_kernel(const float* __restrict__ b2, float* __restrict__ out, int n) {
    int w    = (blockIdx.x * blockDim.x + threadIdx.x) >> 5;
    int lane = threadIdx.x & 31;
    if (w >= n) return;
    float di = g_dinv[w];
    uint uself = g_h2h[(size_t)w * 32 + lane];
    float2 sv = __half22float2(*(__half2*)&uself);
    float2 acc = make_float2(di * sv.x, di * sv.y);
    int j  = g_rowptr[w];
    int jE = g_rowptr[w + 1];
    for (; j + 3 < jE; j += 4) {
        int i0 = g_srcs[j], i1 = g_srcs[j + 1], i2 = g_srcs[j + 2], i3 = g_srcs[j + 3];
        float w0 = g_dinv[i0], w1 = g_dinv[i1], w2 = g_dinv[i2], w3 = g_dinv[i3];
        uint u0 = g_h2h[(size_t)i0 * 32 + lane];
        uint u1 = g_h2h[(size_t)i1 * 32 + lane];
        uint u2 = g_h2h[(size_t)i2 * 32 + lane];
        uint u3 = g_h2h[(size_t)i3 * 32 + lane];
        float2 f0 = __half22float2(*(__half2*)&u0);
        float2 f1 = __half22float2(*(__half2*)&u1);
        float2 f2 = __half22float2(*(__half2*)&u2);
        float2 f3 = __half22float2(*(__half2*)&u3);
        acc.x += w0 * f0.x + w1 * f1.x + w2 * f2.x + w3 * f3.x;
        acc.y += w0 * f0.y + w1 * f1.y + w2 * f2.y + w3 * f3.y;
    }
    for (; j < jE; j++) {
        int   sa = g_srcs[j];
        float wa = g_dinv[sa];
        uint ua = g_h2h[(size_t)sa * 32 + lane];
        float2 fa = __half22float2(*(__half2*)&ua);
        acc.x += wa * fa.x; acc.y += wa * fa.y;
    }
    float2 bb = ((const float2*)b2)[lane];
    float2 r;
    r.x = fmaf(acc.x, di, bb.x);
    r.y = fmaf(acc.y, di, bb.y);
    ((float2*)out)[(size_t)w * 32 + lane] = r;
}

// -------- standalone GEMM2 (A fp16 -> tf32) --------
__global__ void __launch_bounds__(256) gemm2_kernel(
    const __half* __restrict__ A, const float* __restrict__ W,
    __half* __restrict__ C, int M) {
    gemm_body<F2>(A, W, C, M, blockIdx.x);
}

extern "C" void kernel_launch(void* const* d_in, const int* in_sizes, int n_in,
                              void* d_out, int out_size) {
    const float* x  = (const float*)d_in[0];
    const void*  ei = d_in[1];
    const float* W1 = (const float*)d_in[2];
    const float* b1 = (const float*)d_in[3];
    const float* W2 = (const float*)d_in[4];
    const float* b2 = (const float*)d_in[5];
    float* out = (float*)d_out;

    int n = in_sizes[0] / F1;      // 50000
    int E = in_sizes[1] / 2;       // 800000

    void *p_h1h, *p_hrh, *p_h2h;
    cudaGetSymbolAddress(&p_h1h, g_h1h);
    cudaGetSymbolAddress(&p_hrh, g_hrh);
    cudaGetSymbolAddress(&p_h2h, g_h2h);

    detect_zero_kernel<<<(n + 255) / 256, 256>>>(ei, E, n);
    int Gq = (E + 1023) / 1024;               // 4 edges/thread blocks
    hist_kernel<<<Gq, 256>>>(ei, E);
    scan_kernel<<<1, 1024>>>(n);

    int Gg = (n + 127) / 128;                 // GEMM1 blocks
    fused_gemm1_build_kernel<<<Gg + Gq, 256>>>(x, W1, (__half*)p_h1h, n, ei, E, Gg);

    agg1_kernel<<<(n * 32 + 255) / 256, 256>>>(b1, n);
    gemm2_kernel<<<(n + 127) / 128, 256>>>((const __half*)p_hrh, W2, (__half*)p_h2h, n);
    agg2_kernel<<<(n * 32 + 255) / 256, 256>>>(b2, out, n);
}

// round 6
// speedup vs baseline: 2.2150x; 1.0989x over previous
#include <cuda_runtime.h>
#include <cuda_fp16.h>

#define MAX_N 50000
#define MAX_E 800000
#define F1 128
#define F2 64

// -------- scratch --------
__device__ uint2 g_h1h[MAX_N * 32];   // h1 fp16: 128 halves/row
__device__ uint2 g_hrh[MAX_N * 32];   // relu(agg1) fp16: 128 halves/row
__device__ uint  g_h2h[MAX_N * 32];   // h2 fp16: 64 halves/row
__device__ float g_dinv[MAX_N];
__device__ int   g_cnt[MAX_N];        // stays zero between launches (scan re-zeroes)
__device__ int   g_rowptr[MAX_N + 1];
__device__ int   g_cursor[MAX_N];
__device__ int   g_srcs[MAX_E];
__device__ int   g_is64;

// -------- detect edge dtype (int64 vs int32) --------
__global__ void detect_kernel(const void* ei, int E) {
    __shared__ int bad;
    if (threadIdx.x == 0) bad = 0;
    __syncthreads();
    const long long* p = (const long long*)ei;
    int samples = E < 2048 ? E : 2048;
    for (int k = threadIdx.x; k < samples; k += blockDim.x) {
        long long v = p[k];
        if (v < 0 || v >= (long long)MAX_N) bad = 1;
    }
    __syncthreads();
    if (threadIdx.x == 0) g_is64 = bad ? 0 : 1;
}

__device__ __forceinline__ int edge_at(const void* ei, int idx) {
    if (g_is64) return (int)((const long long*)ei)[idx];
    return ((const int*)ei)[idx];
}

// -------- histogram: 4 edges/thread, vectorized int32 path --------
__global__ void hist_kernel(const void* ei, int E) {
    int idx = blockIdx.x * blockDim.x + threadIdx.x;
    int base = idx * 4;
    if (base >= E) return;
    if (!g_is64 && base + 3 < E) {
        const int* dp = (const int*)ei + E;
        int4 d = *(const int4*)(dp + base);
        atomicAdd(&g_cnt[d.x], 1);
        atomicAdd(&g_cnt[d.y], 1);
        atomicAdd(&g_cnt[d.z], 1);
        atomicAdd(&g_cnt[d.w], 1);
    } else {
#pragma unroll
        for (int q = 0; q < 4; q++) {
            int e = base + q;
            if (e < E) atomicAdd(&g_cnt[edge_at(ei, E + e)], 1);
        }
    }
}

// -------- single-block scan (4/thread): rowptr, cursor, dinv; re-zeroes cnt --------
__global__ void scan_kernel(int n) {
    __shared__ int warpsum[32];
    __shared__ int carrysh;
    int t = threadIdx.x, lane = t & 31, w = t >> 5;
    if (t == 0) carrysh = 0;
    __syncthreads();
    int nIter = (n + 4095) / 4096;
    for (int it = 0; it < nIter; it++) {
        int i0 = it * 4096 + t * 4;
        int4 v = make_int4(0, 0, 0, 0);
        if (i0 + 3 < n) {
            v = *(const int4*)&g_cnt[i0];
            *(int4*)&g_cnt[i0] = make_int4(0, 0, 0, 0);   // restore invariant
        } else {
            if (i0     < n) { v.x = g_cnt[i0];     g_cnt[i0]     = 0; }
            if (i0 + 1 < n) { v.y = g_cnt[i0 + 1]; g_cnt[i0 + 1] = 0; }
            if (i0 + 2 < n) { v.z = g_cnt[i0 + 2]; g_cnt[i0 + 2] = 0; }
            if (i0 + 3 < n) { v.w = g_cnt[i0 + 3]; g_cnt[i0 + 3] = 0; }
        }
        int s = v.x + v.y + v.z + v.w;
        int x = s;
#pragma unroll
        for (int o = 1; o < 32; o <<= 1) {
            int y = __shfl_up_sync(~0u, x, o);
            if (lane >= o) x += y;
        }
        if (lane == 31) warpsum[w] = x;
        __syncthreads();
        if (w == 0) {
            int s2 = warpsum[lane];
#pragma unroll
            for (int o = 1; o < 32; o <<= 1) {
                int y = __shfl_up_sync(~0u, s2, o);
                if (lane >= o) s2 += y;
            }
            warpsum[lane] = s2;
        }
        __syncthreads();
        int wbase = w ? warpsum[w - 1] : 0;
        int e0 = carrysh + wbase + x - s;
        int e1 = e0 + v.x, e2 = e1 + v.y, e3 = e2 + v.z;
        if (i0 < n)     { g_rowptr[i0]     = e0; g_cursor[i0]     = e0; g_dinv[i0]     = rsqrtf((float)(v.x + 1)); }
        if (i0 + 1 < n) { g_rowptr[i0 + 1] = e1; g_cursor[i0 + 1] = e1; g_dinv[i0 + 1] = rsqrtf((float)(v.y + 1)); }
        if (i0 + 2 < n) { g_rowptr[i0 + 2] = e2; g_cursor[i0 + 2] = e2; g_dinv[i0 + 2] = rsqrtf((float)(v.z + 1)); }
        if (i0 + 3 < n) { g_rowptr[i0 + 3] = e3; g_cursor[i0 + 3] = e3; g_dinv[i0 + 3] = rsqrtf((float)(v.w + 1)); }
        __syncthreads();
        if (t == 0) carrysh += warpsum[31];
        __syncthreads();
    }
    if (t == 0) g_rowptr[n] = carrysh;
}

// ======== fp16 tensor-core GEMM (m16n8k16 + ldmatrix, swizzled smem) ========
__device__ __forceinline__ void ldsm_x4(unsigned& r0, unsigned& r1, unsigned& r2,
                                        unsigned& r3, unsigned addr) {
    asm volatile("ldmatrix.sync.aligned.m8n8.x4.shared.b16 {%0,%1,%2,%3},[%4];"
                 : "=r"(r0), "=r"(r1), "=r"(r2), "=r"(r3) : "r"(addr));
}
__device__ __forceinline__ void ldsm_x4_t(unsigned& r0, unsigned& r1, unsigned& r2,
                                          unsigned& r3, unsigned addr) {
    asm volatile("ldmatrix.sync.aligned.m8n8.x4.trans.shared.b16 {%0,%1,%2,%3},[%4];"
                 : "=r"(r0), "=r"(r1), "=r"(r2), "=r"(r3) : "r"(addr));
}
__device__ __forceinline__ void mma16816(float* c, unsigned a0, unsigned a1,
                                         unsigned a2, unsigned a3,
                                         unsigned b0, unsigned b1) {
    asm volatile(
        "mma.sync.aligned.m16n8k16.row.col.f32.f16.f16.f32 "
        "{%0,%1,%2,%3},{%4,%5,%6,%7},{%8,%9},{%0,%1,%2,%3};"
        : "+f"(c[0]), "+f"(c[1]), "+f"(c[2]), "+f"(c[3])
        : "r"(a0), "r"(a1), "r"(a2), "r"(a3), "r"(b0), "r"(b1));
}

__device__ __forceinline__ unsigned packh2(float a, float b) {
    __half2 h = __floats2half2_rn(a, b);
    return *(unsigned*)&h;
}

// load one 16B chunk (8 halves) of A row data starting at element offset
__device__ __forceinline__ uint4 loadChunk(const float* A, size_t off) {
    float4 v0 = *(const float4*)(A + off);
    float4 v1 = *(const float4*)(A + off + 4);
    uint4 u;
    u.x = packh2(v0.x, v0.y); u.y = packh2(v0.z, v0.w);
    u.z = packh2(v1.x, v1.y); u.w = packh2(v1.z, v1.w);
    return u;
}
__device__ __forceinline__ uint4 loadChunk(const __half* A, size_t off) {
    return *(const uint4*)(A + off);
}

// C[rowBase:+128, col0:+64] = A[rowBase:+128, 0:128] @ W[0:128, col0:+64]
// K=128 fully resident; one __syncthreads; swizzled chunks for conflict-free ldmatrix.
template<typename TA>
__device__ __forceinline__ void gemm16_body(const TA* __restrict__ A,
                                            const float* __restrict__ W,
                                            __half* __restrict__ C,
                                            int M, int Wwidth, int ldc,
                                            int mt, int nt) {
    __shared__ uint4 sA4[2048];   // 128 rows x 16 chunks (16B) = 32KB
    __shared__ uint4 sB4[1024];   // 128 k-rows x 8 chunks   = 16KB
    int tid = threadIdx.x, lane = tid & 31, warp = tid >> 5;
    int rowBase = mt * 128, col0 = nt * 64;

    // stage A: 2048 chunks, 8 per thread
#pragma unroll
    for (int c = tid; c < 2048; c += 256) {
        int row = c >> 4, kc = c & 15;
        int gr = rowBase + row;
        uint4 u = make_uint4(0, 0, 0, 0);
        if (gr < M) u = loadChunk(A, (size_t)gr * F1 + kc * 8);
        sA4[row * 16 + (kc ^ (row & 7))] = u;
    }
    // stage B (W slice, fp32 -> fp16): 1024 chunks, 4 per thread
#pragma unroll
    for (int c = tid; c < 1024; c += 256) {
        int k = c >> 3, nc = c & 7;
        const float* wp = W + (size_t)k * Wwidth + col0 + nc * 8;
        float4 v0 = *(const float4*)wp;
        float4 v1 = *(const float4*)(wp + 4);
        uint4 u;
        u.x = packh2(v0.x, v0.y); u.y = packh2(v0.z, v0.w);
        u.z = packh2(v1.x, v1.y); u.w = packh2(v1.z, v1.w);
        sB4[k * 8 + (nc ^ (k & 7))] = u;
    }
    __syncthreads();

    float acc[8][4];
#pragma unroll
    for (int i = 0; i < 8; i++)
#pragma unroll
        for (int j = 0; j < 4; j++) acc[i][j] = 0.0f;

    unsigned sAb = (unsigned)__cvta_generic_to_shared(sA4);
    unsigned sBb = (unsigned)__cvta_generic_to_shared(sB4);
    int arow = warp * 16 + (lane & 15);
    int l8 = lane & 7, seg = lane >> 3;

#pragma unroll
    for (int ks = 0; ks < 8; ks++) {
        int akc = ks * 2 + (lane >> 4);
        unsigned a0, a1, a2, a3;
        ldsm_x4(a0, a1, a2, a3, sAb + ((unsigned)(arow * 16 + (akc ^ (arow & 7))) << 4));
        int bk = ks * 16 + (seg & 1) * 8 + l8;
#pragma unroll
        for (int ng = 0; ng < 4; ng++) {
            int bnc = ng * 2 + (seg >> 1);
            unsigned b0, b1, b2, b3;
            ldsm_x4_t(b0, b1, b2, b3, sBb + ((unsigned)(bk * 8 + (bnc ^ (bk & 7))) << 4));
            mma16816(acc[2 * ng],     a0, a1, a2, a3, b0, b1);
            mma16816(acc[2 * ng + 1], a0, a1, a2, a3, b2, b3);
        }
    }
    int g = lane >> 2, tig = lane & 3;
    int r0 = rowBase + warp * 16 + g, r1 = r0 + 8;
#pragma unroll
    for (int nt8 = 0; nt8 < 8; nt8++) {
        int col = col0 + nt8 * 8 + 2 * tig;
        if (r0 < M) *(__half2*)&C[(size_t)r0 * ldc + col] = __floats2half2_rn(acc[nt8][0], acc[nt8][1]);
        if (r1 < M) *(__half2*)&C[(size_t)r1 * ldc + col] = __floats2half2_rn(acc[nt8][2], acc[nt8][3]);
    }
}

// -------- fused: GEMM1 (blocks [0,Gg)) + CSR build (blocks [Gg,...)) --------
__global__ void __launch_bounds__(256) fused_gemm1_build_kernel(
    const float* __restrict__ A, const float* __restrict__ W,
    __half* __restrict__ C, int M, const void* ei, int E, int Gg, int Gm) {
    if ((int)blockIdx.x < Gg) {
        gemm16_body<float>(A, W, C, M, F1, F1, (int)blockIdx.x % Gm, (int)blockIdx.x / Gm);
        return;
    }
    int idx = ((int)blockIdx.x - Gg) * 256 + threadIdx.x;
    int base = idx * 4;
    if (base >= E) return;
    if (!g_is64 && base + 3 < E) {
        const int* sp = (const int*)ei;
        int4 s = *(const int4*)(sp + base);
        int4 d = *(const int4*)(sp + E + base);
        int p0 = atomicAdd(&g_cursor[d.x], 1);
        int p1 = atomicAdd(&g_cursor[d.y], 1);
        int p2 = atomicAdd(&g_cursor[d.z], 1);
        int p3 = atomicAdd(&g_cursor[d.w], 1);
        g_srcs[p0] = s.x; g_srcs[p1] = s.y;
        g_srcs[p2] = s.z; g_srcs[p3] = s.w;
    } else {
#pragma unroll
        for (int q = 0; q < 4; q++) {
            int e = base + q;
            if (e < E) {
                int s = edge_at(ei, e);
                int d = edge_at(ei, E + e);
                g_srcs[atomicAdd(&g_cursor[d], 1)] = s;
            }
        }
    }
}

// -------- standalone GEMM2 (A fp16) --------
__global__ void __launch_bounds__(256) gemm2_kernel(
    const __half* __restrict__ A, const float* __restrict__ W,
    __half* __restrict__ C, int M) {
    gemm16_body<__half>(A, W, C, M, F2, F2, (int)blockIdx.x, 0);
}

// -------- agg layer 1: warp/node, fp16 gathers, 4-way MLP, fused self+bias+relu --------
__global__ void agg1_kernel(const float* __restrict__ b1, int n) {
    int w    = (blockIdx.x * blockDim.x + threadIdx.x) >> 5;
    int lane = threadIdx.x & 31;
    if (w >= n) return;
    float di = g_dinv[w];
    uint2 uself = g_h1h[(size_t)w * 32 + lane];
    float2 s0 = __half22float2(*(__half2*)&uself.x);
    float2 s1 = __half22float2(*(__half2*)&uself.y);
    float4 acc = make_float4(di * s0.x, di * s0.y, di * s1.x, di * s1.y);
    int j  = g_rowptr[w];
    int jE = g_rowptr[w + 1];
    for (; j + 3 < jE; j += 4) {
        int i0 = g_srcs[j], i1 = g_srcs[j + 1], i2 = g_srcs[j + 2], i3 = g_srcs[j + 3];
        float w0 = g_dinv[i0], w1 = g_dinv[i1], w2 = g_dinv[i2], w3 = g_dinv[i3];
        uint2 u0 = g_h1h[(size_t)i0 * 32 + lane];
        uint2 u1 = g_h1h[(size_t)i1 * 32 + lane];
        uint2 u2 = g_h1h[(size_t)i2 * 32 + lane];
        uint2 u3 = g_h1h[(size_t)i3 * 32 + lane];
        float2 a0 = __half22float2(*(__half2*)&u0.x), a1 = __half22float2(*(__half2*)&u0.y);
        float2 c0 = __half22float2(*(__half2*)&u1.x), c1 = __half22float2(*(__half2*)&u1.y);
        float2 d0 = __half22float2(*(__half2*)&u2.x), d1 = __half22float2(*(__half2*)&u2.y);
        float2 e0 = __half22float2(*(__half2*)&u3.x), e1 = __half22float2(*(__half2*)&u3.y);
        acc.x += w0 * a0.x + w1 * c0.x + w2 * d0.x + w3 * e0.x;
        acc.y += w0 * a0.y + w1 * c0.y + w2 * d0.y + w3 * e0.y;
        acc.z += w0 * a1.x + w1 * c1.x + w2 * d1.x + w3 * e1.x;
        acc.w += w0 * a1.y + w1 * c1.y + w2 * d1.y + w3 * e1.y;
    }
    for (; j < jE; j++) {
        int   sa = g_srcs[j];
        float wa = g_dinv[sa];
        uint2 ua = g_h1h[(size_t)sa * 32 + lane];
        float2 a0 = __half22float2(*(__half2*)&ua.x);
        float2 a1 = __half22float2(*(__half2*)&ua.y);
        acc.x += wa * a0.x; acc.y += wa * a0.y;
        acc.z += wa * a1.x; acc.w += wa * a1.y;
    }
    float4 bb = ((const float4*)b1)[lane];
    float rx = fmaxf(fmaf(acc.x, di, bb.x), 0.0f);
    float ry = fmaxf(fmaf(acc.y, di, bb.y), 0.0f);
    float rz = fmaxf(fmaf(acc.z, di, bb.z), 0.0f);
    float rw = fmaxf(fmaf(acc.w, di, bb.w), 0.0f);
    uint2 o;
    *(__half2*)&o.x = __floats2half2_rn(rx, ry);
    *(__half2*)&o.y = __floats2half2_rn(rz, rw);
    g_hrh[(size_t)w * 32 + lane] = o;
}

// -------- agg layer 2: warp/node, fp16 gathers, 4-way MLP, fused self+bias --------
__global__ void agg2_kernel(const float* __restrict__ b2, float* __restrict__ out, int n) {
    int w    = (blockIdx.x * blockDim.x + threadIdx.x) >> 5;
    int lane = threadIdx.x & 31;
    if (w >= n) return;
    float di = g_dinv[w];
    uint uself = g_h2h[(size_t)w * 32 + lane];
    float2 sv = __half22float2(*(__half2*)&uself);
    float2 acc = make_float2(di * sv.x, di * sv.y);
    int j  = g_rowptr[w];
    int jE = g_rowptr[w + 1];
    for (; j + 3 < jE; j += 4) {
        int i0 = g_srcs[j], i1 = g_srcs[j + 1], i2 = g_srcs[j + 2], i3 = g_srcs[j + 3];
        float w0 = g_dinv[i0], w1 = g_dinv[i1], w2 = g_dinv[i2], w3 = g_dinv[i3];
        uint u0 = g_h2h[(size_t)i0 * 32 + lane];
        uint u1 = g_h2h[(size_t)i1 * 32 + lane];
        uint u2 = g_h2h[(size_t)i2 * 32 + lane];
        uint u3 = g_h2h[(size_t)i3 * 32 + lane];
        float2 f0 = __half22float2(*(__half2*)&u0);
        float2 f1 = __half22float2(*(__half2*)&u1);
        float2 f2 = __half22float2(*(__half2*)&u2);
        float2 f3 = __half22float2(*(__half2*)&u3);
        acc.x += w0 * f0.x + w1 * f1.x + w2 * f2.x + w3 * f3.x;
        acc.y += w0 * f0.y + w1 * f1.y + w2 * f2.y + w3 * f3.y;
    }
    for (; j < jE; j++) {
        int   sa = g_srcs[j];
        float wa = g_dinv[sa];
        uint ua = g_h2h[(size_t)sa * 32 + lane];
        float2 fa = __half22float2(*(__half2*)&ua);
        acc.x += wa * fa.x; acc.y += wa * fa.y;
    }
    float2 bb = ((const float2*)b2)[lane];
    float2 r;
    r.x = fmaf(acc.x, di, bb.x);
    r.y = fmaf(acc.y, di, bb.y);
    ((float2*)out)[(size_t)w * 32 + lane] = r;
}

extern "C" void kernel_launch(void* const* d_in, const int* in_sizes, int n_in,
                              void* d_out, int out_size) {
    const float* x  = (const float*)d_in[0];
    const void*  ei = d_in[1];
    const float* W1 = (const float*)d_in[2];
    const float* b1 = (const float*)d_in[3];
    const float* W2 = (const float*)d_in[4];
    const float* b2 = (const float*)d_in[5];
    float* out = (float*)d_out;

    int n = in_sizes[0] / F1;      // 50000
    int E = in_sizes[1] / 2;       // 800000

    void *p_h1h, *p_hrh, *p_h2h;
    cudaGetSymbolAddress(&p_h1h, g_h1h);
    cudaGetSymbolAddress(&p_hrh, g_hrh);
    cudaGetSymbolAddress(&p_h2h, g_h2h);

    detect_kernel<<<1, 256>>>(ei, E);
    int Gq = (E + 1023) / 1024;               // 4 edges/thread blocks
    hist_kernel<<<Gq, 256>>>(ei, E);
    scan_kernel<<<1, 1024>>>(n);

    int Gm = (n + 127) / 128;                 // 391 row tiles
    int Gg = Gm * 2;                          // GEMM1 blocks (two 64-col tiles)
    fused_gemm1_build_kernel<<<Gg + Gq, 256>>>(x, W1, (__half*)p_h1h, n, ei, E, Gg, Gm);

    agg1_kernel<<<(n * 32 + 255) / 256, 256>>>(b1, n);
    gemm2_kernel<<<Gm, 256>>>((const __half*)p_hrh, W2, (__half*)p_h2h, n);
    agg2_kernel<<<(n * 32 + 255) / 256, 256>>>(b2, out, n);
}

// round 9
// speedup vs baseline: 2.3026x; 1.0395x over previous
#include <cuda_runtime.h>
#include <cuda_fp16.h>

#define MAX_N 50000
#define MAX_E 800000
#define F1 128
#define F2 64

// -------- scratch --------
__device__ uint2 g_h1h[MAX_N * 32];   // h1 fp16: 128 halves/row
__device__ uint2 g_hrh[MAX_N * 32];   // relu(agg1) fp16: 128 halves/row
__device__ uint  g_h2h[MAX_N * 32];   // h2 fp16: 64 halves/row
__device__ float g_dinv[MAX_N];
__device__ int   g_cnt[MAX_N];        // stays zero between launches (scan re-zeroes)
__device__ int   g_rowptr[MAX_N + 1];
__device__ int   g_cursor[MAX_N];
__device__ uint2 g_edge[MAX_E];       // (src, dinv[src]) per dst-sorted edge
__device__ int   g_is64;

// -------- detect edge dtype (int64 vs int32) --------
__global__ void detect_kernel(const void* ei, int E) {
    __shared__ int bad;
    if (threadIdx.x == 0) bad = 0;
    __syncthreads();
    const long long* p = (const long long*)ei;
    int samples = E < 2048 ? E : 2048;
    for (int k = threadIdx.x; k < samples; k += blockDim.x) {
        long long v = p[k];
        if (v < 0 || v >= (long long)MAX_N) bad = 1;
    }
    __syncthreads();
    if (threadIdx.x == 0) g_is64 = bad ? 0 : 1;
}

__device__ __forceinline__ int edge_at(const void* ei, int idx) {
    if (g_is64) return (int)((const long long*)ei)[idx];
    return ((const int*)ei)[idx];
}

// -------- single-block scan (4/thread): rowptr, cursor, dinv; re-zeroes cnt --------
__global__ void scan_kernel(int n) {
    __shared__ int warpsum[32];
    __shared__ int carrysh;
    int t = threadIdx.x, lane = t & 31, w = t >> 5;
    if (t == 0) carrysh = 0;
    __syncthreads();
    int nIter = (n + 4095) / 4096;
    for (int it = 0; it < nIter; it++) {
        int i0 = it * 4096 + t * 4;
        int4 v = make_int4(0, 0, 0, 0);
        if (i0 + 3 < n) {
            v = *(const int4*)&g_cnt[i0];
            *(int4*)&g_cnt[i0] = make_int4(0, 0, 0, 0);
        } else {
            if (i0     < n) { v.x = g_cnt[i0];     g_cnt[i0]     = 0; }
            if (i0 + 1 < n) { v.y = g_cnt[i0 + 1]; g_cnt[i0 + 1] = 0; }
            if (i0 + 2 < n) { v.z = g_cnt[i0 + 2]; g_cnt[i0 + 2] = 0; }
            if (i0 + 3 < n) { v.w = g_cnt[i0 + 3]; g_cnt[i0 + 3] = 0; }
        }
        int s = v.x + v.y + v.z + v.w;
        int x = s;
#pragma unroll
        for (int o = 1; o < 32; o <<= 1) {
            int y = __shfl_up_sync(~0u, x, o);
            if (lane >= o) x += y;
        }
        if (lane == 31) warpsum[w] = x;
        __syncthreads();
        if (w == 0) {
            int s2 = warpsum[lane];
#pragma unroll
            for (int o = 1; o < 32; o <<= 1) {
                int y = __shfl_up_sync(~0u, s2, o);
                if (lane >= o) s2 += y;
            }
            warpsum[lane] = s2;
        }
        __syncthreads();
        int wbase = w ? warpsum[w - 1] : 0;
        int e0 = carrysh + wbase + x - s;
        int e1 = e0 + v.x, e2 = e1 + v.y, e3 = e2 + v.z;
        if (i0 < n)     { g_rowptr[i0]     = e0; g_cursor[i0]     = e0; g_dinv[i0]     = rsqrtf((float)(v.x + 1)); }
        if (i0 + 1 < n) { g_rowptr[i0 + 1] = e1; g_cursor[i0 + 1] = e1; g_dinv[i0 + 1] = rsqrtf((float)(v.y + 1)); }
        if (i0 + 2 < n) { g_rowptr[i0 + 2] = e2; g_cursor[i0 + 2] = e2; g_dinv[i0 + 2] = rsqrtf((float)(v.z + 1)); }
        if (i0 + 3 < n) { g_rowptr[i0 + 3] = e3; g_cursor[i0 + 3] = e3; g_dinv[i0 + 3] = rsqrtf((float)(v.w + 1)); }
        __syncthreads();
        if (t == 0) carrysh += warpsum[31];
        __syncthreads();
    }
    if (t == 0) g_rowptr[n] = carrysh;
}

// ======== fp16 tensor-core GEMM (m16n8k16 + ldmatrix, swizzled smem) ========
__device__ __forceinline__ void ldsm_x4(unsigned& r0, unsigned& r1, unsigned& r2,
                                        unsigned& r3, unsigned addr) {
    asm volatile("ldmatrix.sync.aligned.m8n8.x4.shared.b16 {%0,%1,%2,%3},[%4];"
                 : "=r"(r0), "=r"(r1), "=r"(r2), "=r"(r3) : "r"(addr));
}
__device__ __forceinline__ void ldsm_x4_t(unsigned& r0, unsigned& r1, unsigned& r2,
                                          unsigned& r3, unsigned addr) {
    asm volatile("ldmatrix.sync.aligned.m8n8.x4.trans.shared.b16 {%0,%1,%2,%3},[%4];"
                 : "=r"(r0), "=r"(r1), "=r"(r2), "=r"(r3) : "r"(addr));
}
__device__ __forceinline__ void mma16816(float* c, unsigned a0, unsigned a1,
                                         unsigned a2, unsigned a3,
                                         unsigned b0, unsigned b1) {
    asm volatile(
        "mma.sync.aligned.m16n8k16.row.col.f32.f16.f16.f32 "
        "{%0,%1,%2,%3},{%4,%5,%6,%7},{%8,%9},{%0,%1,%2,%3};"
        : "+f"(c[0]), "+f"(c[1]), "+f"(c[2]), "+f"(c[3])
        : "r"(a0), "r"(a1), "r"(a2), "r"(a3), "r"(b0), "r"(b1));
}

__device__ __forceinline__ unsigned packh2(float a, float b) {
    __half2 h = __floats2half2_rn(a, b);
    return *(unsigned*)&h;
}

__device__ __forceinline__ uint4 loadChunk(const float* A, size_t off) {
    float4 v0 = *(const float4*)(A + off);
    float4 v1 = *(const float4*)(A + off + 4);
    uint4 u;
    u.x = packh2(v0.x, v0.y); u.y = packh2(v0.z, v0.w);
    u.z = packh2(v1.x, v1.y); u.w = packh2(v1.z, v1.w);
    return u;
}
__device__ __forceinline__ uint4 loadChunk(const __half* A, size_t off) {
    return *(const uint4*)(A + off);
}

// C[mt*128:+128, 0:BN] = A[.., 0:128] @ W[0:128, 0:BN]; K fully resident, 1 sync.
template<typename TA, int BN>
__device__ __forceinline__ void gemm16_body(const TA* __restrict__ A,
                                            const float* __restrict__ W,
                                            __half* __restrict__ C,
                                            int M, int mt) {
    constexpr int NCH = BN / 8;    // 16B chunks per B row
    constexpr int NG  = BN / 16;   // n-groups of 16 cols
    __shared__ uint4 sA4[2048];          // 128 x 16 chunks = 32KB
    __shared__ uint4 sB4[128 * NCH];     // 128 k-rows x NCH chunks
    int tid = threadIdx.x, lane = tid & 31, warp = tid >> 5;
    int rowBase = mt * 128;

#pragma unroll
    for (int c = tid; c < 2048; c += 256) {
        int row = c >> 4, kc = c & 15;
        int gr = rowBase + row;
        uint4 u = make_uint4(0, 0, 0, 0);
        if (gr < M) u = loadChunk(A, (size_t)gr * F1 + kc * 8);
        sA4[row * 16 + (kc ^ (row & 7))] = u;
    }
#pragma unroll
    for (int c = tid; c < 128 * NCH; c += 256) {
        int k = c / NCH, nc = c % NCH;
        const float* wp = W + (size_t)k * BN + nc * 8;
        float4 v0 = *(const float4*)wp;
        float4 v1 = *(const float4*)(wp + 4);
        uint4 u;
        u.x = packh2(v0.x, v0.y); u.y = packh2(v0.z, v0.w);
        u.z = packh2(v1.x, v1.y); u.w = packh2(v1.z, v1.w);
        sB4[k * NCH + (nc ^ (k & 7))] = u;
    }
    __syncthreads();

    float acc[2 * NG][4];
#pragma unroll
    for (int i = 0; i < 2 * NG; i++)
#pragma unroll
        for (int j = 0; j < 4; j++) acc[i][j] = 0.0f;

    unsigned sAb = (unsigned)__cvta_generic_to_shared(sA4);
    unsigned sBb = (unsigned)__cvta_generic_to_shared(sB4);
    int arow = warp * 16 + (lane & 15);
    int l8 = lane & 7, seg = lane >> 3;

#pragma unroll
    for (int ks = 0; ks < 8; ks++) {
        int akc = ks * 2 + (lane >> 4);
        unsigned a0, a1, a2, a3;
        ldsm_x4(a0, a1, a2, a3, sAb + ((unsigned)(arow * 16 + (akc ^ (arow & 7))) << 4));
        int bk = ks * 16 + (seg & 1) * 8 + l8;
#pragma unroll
        for (int ng = 0; ng < NG; ng++) {
            int bnc = ng * 2 + (seg >> 1);
            unsigned b0, b1, b2, b3;
            ldsm_x4_t(b0, b1, b2, b3, sBb + ((unsigned)(bk * NCH + (bnc ^ (bk & 7))) << 4));
            mma16816(acc[2 * ng],     a0, a1, a2, a3, b0, b1);
            mma16816(acc[2 * ng + 1], a0, a1, a2, a3, b2, b3);
        }
    }
    int g = lane >> 2, tig = lane & 3;
    int r0 = rowBase + warp * 16 + g, r1 = r0 + 8;
#pragma unroll
    for (int nt = 0; nt < 2 * NG; nt++) {
        int col = nt * 8 + 2 * tig;
        if (r0 < M) *(__half2*)&C[(size_t)r0 * BN + col] = __floats2half2_rn(acc[nt][0], acc[nt][1]);
        if (r1 < M) *(__half2*)&C[(size_t)r1 * BN + col] = __floats2half2_rn(acc[nt][2], acc[nt][3]);
    }
}

// -------- fused A: GEMM1 rows [0,Gg) tiles + histogram --------
__global__ void __launch_bounds__(256) fused_hist_gemm1_kernel(
    const float* __restrict__ A, const float* __restrict__ W,
    __half* __restrict__ C, int M, const void* ei, int E, int Gg) {
    if ((int)blockIdx.x < Gg) {
        gemm16_body<float, F1>(A, W, C, M, (int)blockIdx.x);
        return;
    }
    int idx = ((int)blockIdx.x - Gg) * 256 + threadIdx.x;
    int base = idx * 4;
    if (base >= E) return;
    if (!g_is64 && base + 3 < E) {
        const int* dp = (const int*)ei + E;
        int4 d = *(const int4*)(dp + base);
        atomicAdd(&g_cnt[d.x], 1);
        atomicAdd(&g_cnt[d.y], 1);
        atomicAdd(&g_cnt[d.z], 1);
        atomicAdd(&g_cnt[d.w], 1);
    } else {
#pragma unroll
        for (int q = 0; q < 4; q++) {
            int e = base + q;
            if (e < E) atomicAdd(&g_cnt[edge_at(ei, E + e)], 1);
        }
    }
}

// -------- fused B: GEMM1 remaining row tiles + CSR build (edge records) --------
__global__ void __launch_bounds__(256) fused_build_gemm1_kernel(
    const float* __restrict__ A, const float* __restrict__ W,
    __half* __restrict__ C, int M, const void* ei, int E, int Gg, int mt0) {
    if ((int)blockIdx.x < Gg) {
        gemm16_body<float, F1>(A, W, C, M, mt0 + (int)blockIdx.x);
        return;
    }
    int idx = ((int)blockIdx.x - Gg) * 256 + threadIdx.x;
    int base = idx * 4;
    if (base >= E) return;
    if (!g_is64 && base + 3 < E) {
        const int* sp = (const int*)ei;
        int4 s = *(const int4*)(sp + base);
        int4 d = *(const int4*)(sp + E + base);
        float w0 = g_dinv[s.x], w1 = g_dinv[s.y], w2 = g_dinv[s.z], w3 = g_dinv[s.w];
        int p0 = atomicAdd(&g_cursor[d.x], 1);
        int p1 = atomicAdd(&g_cursor[d.y], 1);
        int p2 = atomicAdd(&g_cursor[d.z], 1);
        int p3 = atomicAdd(&g_cursor[d.w], 1);
        g_edge[p0] = make_uint2((unsigned)s.x, __float_as_uint(w0));
        g_edge[p1] = make_uint2((unsigned)s.y, __float_as_uint(w1));
        g_edge[p2] = make_uint2((unsigned)s.z, __float_as_uint(w2));
        g_edge[p3] = make_uint2((unsigned)s.w, __float_as_uint(w3));
    } else {
#pragma unroll
        for (int q = 0; q < 4; q++) {
            int e = base + q;
            if (e < E) {
                int s = edge_at(ei, e);
                int d = edge_at(ei, E + e);
                float ws = g_dinv[s];
                g_edge[atomicAdd(&g_cursor[d], 1)] = make_uint2((unsigned)s, __float_as_uint(ws));
            }
        }
    }
}

// -------- standalone GEMM2 (A fp16) --------
__global__ void __launch_bounds__(256) gemm2_kernel(
    const __half* __restrict__ A, const float* __restrict__ W,
    __half* __restrict__ C, int M) {
    gemm16_body<__half, F2>(A, W, C, M, (int)blockIdx.x);
}

// -------- agg layer 1: warp/node, edge records, 4-way MLP, fused self+bias+relu --------
__global__ void agg1_kernel(const float* __restrict__ b1, int n) {
    int w    = (blockIdx.x * blockDim.x + threadIdx.x) >> 5;
    int lane = threadIdx.x & 31;
    if (w >= n) return;
    float di = g_dinv[w];
    uint2 uself = g_h1h[(size_t)w * 32 + lane];
    float2 s0 = __half22float2(*(__half2*)&uself.x);
    float2 s1 = __half22float2(*(__half2*)&uself.y);
    float4 acc = make_float4(di * s0.x, di * s0.y, di * s1.x, di * s1.y);
    int j  = g_rowptr[w];
    int jE = g_rowptr[w + 1];
    for (; j + 3 < jE; j += 4) {
        uint2 r0 = g_edge[j],     r1 = g_edge[j + 1];
        uint2 r2 = g_edge[j + 2], r3 = g_edge[j + 3];
        float w0 = __uint_as_float(r0.y), w1 = __uint_as_float(r1.y);
        float w2 = __uint_as_float(r2.y), w3 = __uint_as_float(r3.y);
        uint2 u0 = g_h1h[(size_t)r0.x * 32 + lane];
        uint2 u1 = g_h1h[(size_t)r1.x * 32 + lane];
        uint2 u2 = g_h1h[(size_t)r2.x * 32 + lane];
        uint2 u3 = g_h1h[(size_t)r3.x * 32 + lane];
        float2 a0 = __half22float2(*(__half2*)&u0.x), a1 = __half22float2(*(__half2*)&u0.y);
        float2 c0 = __half22float2(*(__half2*)&u1.x), c1 = __half22float2(*(__half2*)&u1.y);
        float2 d0 = __half22float2(*(__half2*)&u2.x), d1 = __half22float2(*(__half2*)&u2.y);
        float2 e0 = __half22float2(*(__half2*)&u3.x), e1 = __half22float2(*(__half2*)&u3.y);
        acc.x += w0 * a0.x + w1 * c0.x + w2 * d0.x + w3 * e0.x;
        acc.y += w0 * a0.y + w1 * c0.y + w2 * d0.y + w3 * e0.y;
        acc.z += w0 * a1.x + w1 * c1.x + w2 * d1.x + w3 * e1.x;
        acc.w += w0 * a1.y + w1 * c1.y + w2 * d1.y + w3 * e1.y;
    }
    for (; j < jE; j++) {
        uint2 rr = g_edge[j];
        float wa = __uint_as_float(rr.y);
        uint2 ua = g_h1h[(size_t)rr.x * 32 + lane];
        float2 a0 = __half22float2(*(__half2*)&ua.x);
        float2 a1 = __half22float2(*(__half2*)&ua.y);
        acc.x += wa * a0.x; acc.y += wa * a0.y;
        acc.z += wa * a1.x; acc.w += wa * a1.y;
    }
    float4 bb = ((const float4*)b1)[lane];
    float rx = fmaxf(fmaf(acc.x, di, bb.x), 0.0f);
    float ry = fmaxf(fmaf(acc.y, di, bb.y), 0.0f);
    float rz = fmaxf(fmaf(acc.z, di, bb.z), 0.0f);
    float rw = fmaxf(fmaf(acc.w, di, bb.w), 0.0f);
    uint2 o;
    *(__half2*)&o.x = __floats2half2_rn(rx, ry);
    *(__half2*)&o.y = __floats2half2_rn(rz, rw);
    g_hrh[(size_t)w * 32 + lane] = o;
}

// -------- agg layer 2: warp/node, edge records, 4-way MLP, fused self+bias --------
__global__ void agg2_kernel(const float* __restrict__ b2, float* __restrict__ out, int n) {
    int w    = (blockIdx.x * blockDim.x + threadIdx.x) >> 5;
    int lane = threadIdx.x & 31;
    if (w >= n) return;
    float di = g_dinv[w];
    uint uself = g_h2h[(size_t)w * 32 + lane];
    float2 sv = __half22float2(*(__half2*)&uself);
    float2 acc = make_float2(di * sv.x, di * sv.y);
    int j  = g_rowptr[w];
    int jE = g_rowptr[w + 1];
    for (; j + 3 < jE; j += 4) {
        uint2 r0 = g_edge[j],     r1 = g_edge[j + 1];
        uint2 r2 = g_edge[j + 2], r3 = g_edge[j + 3];
        float w0 = __uint_as_float(r0.y), w1 = __uint_as_float(r1.y);
        float w2 = __uint_as_float(r2.y), w3 = __uint_as_float(r3.y);
        uint u0 = g_h2h[(size_t)r0.x * 32 + lane];
        uint u1 = g_h2h[(size_t)r1.x * 32 + lane];
        uint u2 = g_h2h[(size_t)r2.x * 32 + lane];
        uint u3 = g_h2h[(size_t)r3.x * 32 + lane];
        float2 f0 = __half22float2(*(__half2*)&u0);
        float2 f1 = __half22float2(*(__half2*)&u1);
        float2 f2 = __half22float2(*(__half2*)&u2);
        float2 f3 = __half22float2(*(__half2*)&u3);
        acc.x += w0 * f0.x + w1 * f1.x + w2 * f2.x + w3 * f3.x;
        acc.y += w0 * f0.y + w1 * f1.y + w2 * f2.y + w3 * f3.y;
    }
    for (; j < jE; j++) {
        uint2 rr = g_edge[j];
        float wa = __uint_as_float(rr.y);
        uint ua = g_h2h[(size_t)rr.x * 32 + lane];
        float2 fa = __half22float2(*(__half2*)&ua);
        acc.x += wa * fa.x; acc.y += wa * fa.y;
    }
    float2 bb = ((const float2*)b2)[lane];
    float2 r;
    r.x = fmaf(acc.x, di, bb.x);
    r.y = fmaf(acc.y, di, bb.y);
    ((float2*)out)[(size_t)w * 32 + lane] = r;
}

extern "C" void kernel_launch(void* const* d_in, const int* in_sizes, int n_in,
                              void* d_out, int out_size) {
    const float* x  = (const float*)d_in[0];
    const void*  ei = d_in[1];
    const float* W1 = (const float*)d_in[2];
    const float* b1 = (const float*)d_in[3];
    const float* W2 = (const float*)d_in[4];
    const float* b2 = (const float*)d_in[5];
    float* out = (float*)d_out;

    int n = in_sizes[0] / F1;      // 50000
    int E = in_sizes[1] / 2;       // 800000

    void *p_h1h, *p_hrh, *p_h2h;
    cudaGetSymbolAddress(&p_h1h, g_h1h);
    cudaGetSymbolAddress(&p_hrh, g_hrh);
    cudaGetSymbolAddress(&p_h2h, g_h2h);

    detect_kernel<<<1, 256>>>(ei, E);

    int Gq  = (E + 1023) / 1024;              // aux blocks: 4 edges/thread
    int Gm  = (n + 127) / 128;                // 391 GEMM1 row tiles
    int Gm1 = (Gm * 2) / 5;                   // rows hidden behind hist
    int Gm2 = Gm - Gm1;                       // rows hidden behind build

    fused_hist_gemm1_kernel<<<Gm1 + Gq, 256>>>(x, W1, (__half*)p_h1h, n, ei, E, Gm1);
    scan_kernel<<<1, 1024>>>(n);
    fused_build_gemm1_kernel<<<Gm2 + Gq, 256>>>(x, W1, (__half*)p_h1h, n, ei, E, Gm2, Gm1);

    agg1_kernel<<<(n * 32 + 255) / 256, 256>>>(b1, n);
    gemm2_kernel<<<Gm, 256>>>((const __half*)p_hrh, W2, (__half*)p_h2h, n);
    agg2_kernel<<<(n * 32 + 255) / 256, 256>>>(b2, out, n);
}